// round 1
// baseline (speedup 1.0000x reference)
#include <cuda_runtime.h>
#include <math.h>
#include <stdint.h>

#define DM 1024
#define NH 16
#define HD 64
#define NB 2
#define SQ 2048
#define MR (NB*SQ)   // 4096 token rows

// ---------------- scratch (device globals: allocation-free) ----------------
__device__ float g_qn[(size_t)MR*DM];
__device__ float g_kn[(size_t)MR*DM];
__device__ float g_vn[(size_t)MR*DM];
__device__ float g_q [(size_t)MR*DM];
__device__ float g_k [(size_t)MR*DM];
__device__ float g_v [(size_t)MR*DM];
__device__ float g_ctx[(size_t)MR*DM];
__device__ float g_wb[(size_t)NB*SQ*SQ];   // pre-scaled relation bias

// ---------------- tf32 helpers ----------------
static __device__ __forceinline__ unsigned f2tf(float x){
    unsigned u; asm("cvt.rna.tf32.f32 %0, %1;" : "=r"(u) : "f"(x)); return u;
}
static __device__ __forceinline__ float f2tff(float x){ return __uint_as_float(f2tf(x)); }

static __device__ __forceinline__ void mma8(float* d,
        unsigned a0, unsigned a1, unsigned a2, unsigned a3,
        unsigned b0, unsigned b1){
    asm volatile("mma.sync.aligned.m16n8k8.row.col.f32.tf32.tf32.f32 "
        "{%0,%1,%2,%3}, {%4,%5,%6,%7}, {%8,%9}, {%0,%1,%2,%3};\n"
        : "+f"(d[0]), "+f"(d[1]), "+f"(d[2]), "+f"(d[3])
        : "r"(a0), "r"(a1), "r"(a2), "r"(a3), "r"(b0), "r"(b1));
}

// ---------------- LayerNorm (shared gamma/beta) ----------------
__global__ __launch_bounds__(256) void ln_kernel(
    const float* __restrict__ q, const float* __restrict__ k, const float* __restrict__ v,
    const float* __restrict__ gamma, const float* __restrict__ beta)
{
    int row = blockIdx.x;
    const float* src; float* dst;
    if (blockIdx.y == 0){ src = q; dst = g_qn; }
    else if (blockIdx.y == 1){ src = k; dst = g_kn; }
    else { src = v; dst = g_vn; }

    const float4 xv = ((const float4*)(src + (size_t)row*DM))[threadIdx.x];
    float s  = xv.x + xv.y + xv.z + xv.w;
    float sq = xv.x*xv.x + xv.y*xv.y + xv.z*xv.z + xv.w*xv.w;
    #pragma unroll
    for (int o = 16; o; o >>= 1){
        s  += __shfl_xor_sync(0xffffffffu, s,  o);
        sq += __shfl_xor_sync(0xffffffffu, sq, o);
    }
    __shared__ float rs[8], rq[8];
    int w = threadIdx.x >> 5, lane = threadIdx.x & 31;
    if (!lane){ rs[w] = s; rq[w] = sq; }
    __syncthreads();
    if (threadIdx.x == 0){
        float ts = 0.f, tq = 0.f;
        #pragma unroll
        for (int i = 0; i < 8; ++i){ ts += rs[i]; tq += rq[i]; }
        float mu  = ts * (1.f/DM);
        float var = tq * (1.f/DM) - mu*mu;
        rs[0] = mu; rq[0] = rsqrtf(var + 1e-5f);
    }
    __syncthreads();
    float mu = rs[0], rstd = rq[0];
    const float4 g4 = ((const float4*)gamma)[threadIdx.x];
    const float4 b4 = ((const float4*)beta )[threadIdx.x];
    float4 o;
    o.x = (xv.x - mu)*rstd*g4.x + b4.x;
    o.y = (xv.y - mu)*rstd*g4.y + b4.y;
    o.z = (xv.z - mu)*rstd*g4.z + b4.z;
    o.w = (xv.w - mu)*rstd*g4.w + b4.w;
    ((float4*)(dst + (size_t)row*DM))[threadIdx.x] = o;
}

// ---------------- relation bias: g_wb = (tag_rel @ softmax(rel_type_w)) * 0.1*sigmoid(rel_scale) ----------------
__global__ __launch_bounds__(256) void wbias_kernel(
    const float4* __restrict__ tr, const float* __restrict__ rtw, const float* __restrict__ rsc)
{
    float w0 = rtw[0], w1 = rtw[1], w2 = rtw[2], w3 = rtw[3];
    float mx = fmaxf(fmaxf(w0,w1), fmaxf(w2,w3));
    float e0 = expf(w0-mx), e1 = expf(w1-mx), e2 = expf(w2-mx), e3 = expf(w3-mx);
    float bs = 0.1f / (1.f + expf(-rsc[0]));
    float inv = bs / (e0+e1+e2+e3);
    float r0 = e0*inv, r1 = e1*inv, r2 = e2*inv, r3 = e3*inv;
    size_t i = (size_t)blockIdx.x*256 + threadIdx.x;
    float4 t = tr[i];
    g_wb[i] = t.x*r0 + t.y*r1 + t.z*r2 + t.w*r3;
}

// ---------------- TF32 GEMM: C[4096,1024] = A[4096,1024] @ W[1024,1024]^T + bias ----------------
__global__ __launch_bounds__(256) void gemm_tf32(
    const float* __restrict__ A, const float* __restrict__ W,
    const float* __restrict__ bias, float* __restrict__ C)
{
    __shared__ __align__(16) float As[2][128][20];
    __shared__ __align__(16) float Bs[2][128][20];
    const int tid = threadIdx.x, lane = tid & 31, wid = tid >> 5;
    const int wm = wid >> 1, wn = wid & 1;
    const int bm = blockIdx.y*128, bn = blockIdx.x*128;

    float acc[2][8][4];
    #pragma unroll
    for (int mt = 0; mt < 2; ++mt)
        #pragma unroll
        for (int nt = 0; nt < 8; ++nt)
            #pragma unroll
            for (int e = 0; e < 4; ++e) acc[mt][nt][e] = 0.f;

    const int lr = tid >> 2, lc = (tid & 3)*4;
    float4 ra[2], rb[2];

    #define FETCH(kt) do { \
        const float* Ap = A + (size_t)(bm+lr)*1024 + (kt)*16 + lc; \
        ra[0] = *(const float4*)Ap; ra[1] = *(const float4*)(Ap + (size_t)64*1024); \
        const float* Wp = W + (size_t)(bn+lr)*1024 + (kt)*16 + lc; \
        rb[0] = *(const float4*)Wp; rb[1] = *(const float4*)(Wp + (size_t)64*1024); \
    } while(0)
    #define STORE(st) do { \
        *(float4*)&As[st][lr   ][lc] = make_float4(f2tff(ra[0].x), f2tff(ra[0].y), f2tff(ra[0].z), f2tff(ra[0].w)); \
        *(float4*)&As[st][lr+64][lc] = make_float4(f2tff(ra[1].x), f2tff(ra[1].y), f2tff(ra[1].z), f2tff(ra[1].w)); \
        *(float4*)&Bs[st][lr   ][lc] = make_float4(f2tff(rb[0].x), f2tff(rb[0].y), f2tff(rb[0].z), f2tff(rb[0].w)); \
        *(float4*)&Bs[st][lr+64][lc] = make_float4(f2tff(rb[1].x), f2tff(rb[1].y), f2tff(rb[1].z), f2tff(rb[1].w)); \
    } while(0)

    FETCH(0); STORE(0); __syncthreads();

    for (int kt = 0; kt < 64; ++kt){
        const int cur = kt & 1;
        if (kt < 63) FETCH(kt+1);
        #pragma unroll
        for (int ks = 0; ks < 2; ++ks){
            const int k0 = ks*8 + (lane & 3);
            unsigned af[2][4], bf[8][2];
            #pragma unroll
            for (int mt = 0; mt < 2; ++mt){
                int r = wm*32 + mt*16 + (lane >> 2);
                af[mt][0] = __float_as_uint(As[cur][r  ][k0  ]);
                af[mt][1] = __float_as_uint(As[cur][r+8][k0  ]);
                af[mt][2] = __float_as_uint(As[cur][r  ][k0+4]);
                af[mt][3] = __float_as_uint(As[cur][r+8][k0+4]);
            }
            #pragma unroll
            for (int nt = 0; nt < 8; ++nt){
                int n = wn*64 + nt*8 + (lane >> 2);
                bf[nt][0] = __float_as_uint(Bs[cur][n][k0  ]);
                bf[nt][1] = __float_as_uint(Bs[cur][n][k0+4]);
            }
            #pragma unroll
            for (int mt = 0; mt < 2; ++mt)
                #pragma unroll
                for (int nt = 0; nt < 8; ++nt)
                    mma8(acc[mt][nt], af[mt][0], af[mt][1], af[mt][2], af[mt][3],
                         bf[nt][0], bf[nt][1]);
        }
        if (kt < 63) STORE(cur ^ 1);
        __syncthreads();
    }
    #undef FETCH
    #undef STORE

    #pragma unroll
    for (int mt = 0; mt < 2; ++mt)
        #pragma unroll
        for (int nt = 0; nt < 8; ++nt)
            #pragma unroll
            for (int e = 0; e < 4; ++e){
                int r = bm + wm*32 + mt*16 + (lane >> 2) + ((e >> 1) << 3);
                int c = bn + wn*64 + nt*8 + (lane & 3)*2 + (e & 1);
                C[(size_t)r*1024 + c] = acc[mt][nt][e] + bias[c];
            }
}

// ---------------- fused attention: QK^T + bias + mask + softmax + weights-out + PV ----------------
// CTA = (q_tile of 16 rows, head, batch). Full 16x2048 score row lives in SMEM.
#define AT_SS 2052   // score row stride (pad: conflict-free mma A reads)
#define AT_KS 72     // K/V/Q tile stride (pad: conflict-free mma B reads)

__global__ __launch_bounds__(256) void attn_kernel(
    const int* __restrict__ mask, float* __restrict__ attnw)
{
    extern __shared__ float smem[];
    float* sc = smem;                       // [16][AT_SS]
    float* Qs = smem + 16*AT_SS;            // [16][AT_KS]
    float* KV = Qs + 16*AT_KS;              // [64][AT_KS]

    const int b = blockIdx.z, h = blockIdx.y, q0 = blockIdx.x*16;
    const int tid = threadIdx.x, lane = tid & 31, w = tid >> 5;

    // load + tf32-round Q tile (16 x 64)
    {
        int r = tid >> 4, c4 = tid & 15;
        const float* qb = g_q + ((size_t)(b*SQ + q0 + r))*DM + h*HD;
        float4 v = *(const float4*)(qb + c4*4);
        *(float4*)&Qs[r*AT_KS + c4*4] =
            make_float4(f2tff(v.x), f2tff(v.y), f2tff(v.z), f2tff(v.w));
    }

    // ---- Phase 1: scores = QK^T/8 + bias, masked, into SMEM ----
    for (int kc = 0; kc < 32; ++kc){
        __syncthreads();
        {
            const float* kb = g_k + ((size_t)(b*SQ + kc*64))*DM + h*HD;
            #pragma unroll
            for (int j = 0; j < 4; ++j){
                int f = tid + j*256, r = f >> 4, c4 = f & 15;
                float4 v = *(const float4*)(kb + (size_t)r*DM + c4*4);
                *(float4*)&KV[r*AT_KS + c4*4] =
                    make_float4(f2tff(v.x), f2tff(v.y), f2tff(v.z), f2tff(v.w));
            }
        }
        __syncthreads();
        float acc[4] = {0.f, 0.f, 0.f, 0.f};
        #pragma unroll
        for (int ks = 0; ks < 8; ++ks){
            const int ak = ks*8 + (lane & 3);
            const int ar = lane >> 2;
            unsigned a0 = __float_as_uint(Qs[ ar   *AT_KS + ak  ]);
            unsigned a1 = __float_as_uint(Qs[(ar+8)*AT_KS + ak  ]);
            unsigned a2 = __float_as_uint(Qs[ ar   *AT_KS + ak+4]);
            unsigned a3 = __float_as_uint(Qs[(ar+8)*AT_KS + ak+4]);
            const int bn = w*8 + (lane >> 2);
            unsigned b0 = __float_as_uint(KV[bn*AT_KS + ak  ]);
            unsigned b1 = __float_as_uint(KV[bn*AT_KS + ak+4]);
            mma8(acc, a0, a1, a2, a3, b0, b1);
        }
        const int r0 = lane >> 2, cb = (lane & 3)*2;
        #pragma unroll
        for (int e = 0; e < 4; ++e){
            int r = r0 + ((e >> 1) << 3);
            int c = cb + (e & 1);
            int gcol = kc*64 + w*8 + c;
            float s = acc[e]*0.125f +
                      g_wb[((size_t)b*SQ + q0 + r)*SQ + gcol];
            if (mask[b*SQ + gcol] == 0) s = -1e9f;
            sc[r*AT_SS + gcol] = s;
        }
    }
    __syncthreads();

    // ---- Phase 2: row softmax + stream attn_weights to gmem ----
    #pragma unroll
    for (int rr = 2*w; rr <= 2*w + 1; ++rr){
        float* srow = sc + rr*AT_SS;
        float m = -1e30f;
        for (int i = lane; i < 2048; i += 32) m = fmaxf(m, srow[i]);
        #pragma unroll
        for (int o = 16; o; o >>= 1) m = fmaxf(m, __shfl_xor_sync(0xffffffffu, m, o));
        float sum = 0.f;
        for (int i = lane; i < 2048; i += 32){
            float e = __expf(srow[i] - m);
            srow[i] = e;
            sum += e;
        }
        #pragma unroll
        for (int o = 16; o; o >>= 1) sum += __shfl_xor_sync(0xffffffffu, sum, o);
        float inv = 1.f / sum;
        float* out = attnw + (((size_t)(b*NH + h)*SQ + q0 + rr) * SQ);
        for (int i = lane; i < 512; i += 32){
            float4 p = *(float4*)&srow[i*4];
            p.x *= inv; p.y *= inv; p.z *= inv; p.w *= inv;
            *(float4*)&srow[i*4] = p;
            *(float4*)&out[i*4]  = p;
        }
    }

    // ---- Phase 3: ctx = P @ V ----
    float oacc[4] = {0.f, 0.f, 0.f, 0.f};
    for (int kc = 0; kc < 32; ++kc){
        __syncthreads();
        {
            const float* vb = g_v + ((size_t)(b*SQ + kc*64))*DM + h*HD;
            #pragma unroll
            for (int j = 0; j < 4; ++j){
                int f = tid + j*256, r = f >> 4, c4 = f & 15;
                float4 v = *(const float4*)(vb + (size_t)r*DM + c4*4);
                *(float4*)&KV[r*AT_KS + c4*4] =
                    make_float4(f2tff(v.x), f2tff(v.y), f2tff(v.z), f2tff(v.w));
            }
        }
        __syncthreads();
        #pragma unroll
        for (int ks = 0; ks < 8; ++ks){
            const int akc = kc*64 + ks*8 + (lane & 3);
            const int ar = lane >> 2;
            unsigned a0 = f2tf(sc[ ar   *AT_SS + akc  ]);
            unsigned a1 = f2tf(sc[(ar+8)*AT_SS + akc  ]);
            unsigned a2 = f2tf(sc[ ar   *AT_SS + akc+4]);
            unsigned a3 = f2tf(sc[(ar+8)*AT_SS + akc+4]);
            const int bk = ks*8 + (lane & 3);
            const int bn = w*8 + (lane >> 2);
            unsigned b0 = __float_as_uint(KV[ bk   *AT_KS + bn]);
            unsigned b1 = __float_as_uint(KV[(bk+4)*AT_KS + bn]);
            mma8(oacc, a0, a1, a2, a3, b0, b1);
        }
    }
    {
        const int r0 = lane >> 2, cb = (lane & 3)*2;
        #pragma unroll
        for (int e = 0; e < 4; ++e){
            int r = r0 + ((e >> 1) << 3);
            int c = w*8 + cb + (e & 1);
            g_ctx[((size_t)(b*SQ + q0 + r))*DM + h*HD + c] = oacc[e];
        }
    }
}

// ---------------- launcher ----------------
extern "C" void kernel_launch(void* const* d_in, const int* in_sizes, int n_in,
                              void* d_out, int out_size)
{
    const float* q     = (const float*)d_in[0];
    const float* k     = (const float*)d_in[1];
    const float* v     = (const float*)d_in[2];
    const int*   mask  = (const int*)  d_in[3];
    const float* tagr  = (const float*)d_in[4];
    const float* gamma = (const float*)d_in[5];
    const float* beta  = (const float*)d_in[6];
    const float* Wq    = (const float*)d_in[7];
    const float* bq    = (const float*)d_in[8];
    const float* Wk    = (const float*)d_in[9];
    const float* bk    = (const float*)d_in[10];
    const float* Wv    = (const float*)d_in[11];
    const float* bv    = (const float*)d_in[12];
    const float* Wo    = (const float*)d_in[13];
    const float* bo    = (const float*)d_in[14];
    const float* rtw   = (const float*)d_in[15];
    const float* rsc   = (const float*)d_in[16];

    float* out   = (float*)d_out;
    float* attnw = out + (size_t)MR*DM;

    float *p_qn, *p_kn, *p_vn, *p_q, *p_k, *p_v, *p_ctx;
    cudaGetSymbolAddress((void**)&p_qn, g_qn);
    cudaGetSymbolAddress((void**)&p_kn, g_kn);
    cudaGetSymbolAddress((void**)&p_vn, g_vn);
    cudaGetSymbolAddress((void**)&p_q,  g_q);
    cudaGetSymbolAddress((void**)&p_k,  g_k);
    cudaGetSymbolAddress((void**)&p_v,  g_v);
    cudaGetSymbolAddress((void**)&p_ctx, g_ctx);

    ln_kernel<<<dim3(MR, 3), 256>>>(q, k, v, gamma, beta);
    wbias_kernel<<<(NB*SQ*SQ)/256, 256>>>((const float4*)tagr, rtw, rsc);

    gemm_tf32<<<dim3(8, 32), 256>>>(p_qn, Wq, bq, p_q);
    gemm_tf32<<<dim3(8, 32), 256>>>(p_kn, Wk, bk, p_k);
    gemm_tf32<<<dim3(8, 32), 256>>>(p_vn, Wv, bv, p_v);

    const int shbytes = (16*AT_SS + 16*AT_KS + 64*AT_KS) * 4;
    cudaFuncSetAttribute(attn_kernel, cudaFuncAttributeMaxDynamicSharedMemorySize, 160*1024);
    attn_kernel<<<dim3(SQ/16, NH, NB), 256, shbytes>>>(mask, attnw);

    gemm_tf32<<<dim3(8, 32), 256>>>(p_ctx, Wo, bo, out);
}

// round 4
// speedup vs baseline: 2.0840x; 2.0840x over previous
#include <cuda_runtime.h>
#include <math.h>
#include <stdint.h>

#define DM 1024
#define NH 16
#define HD 64
#define NB 2
#define SQ 2048
#define MR (NB*SQ)   // 4096 token rows

// ---------------- scratch (device globals: allocation-free) ----------------
__device__ float g_qn[(size_t)MR*DM];
__device__ float g_kn[(size_t)MR*DM];
__device__ float g_vn[(size_t)MR*DM];
__device__ float g_q [(size_t)MR*DM];
__device__ float g_k [(size_t)MR*DM];
__device__ float g_v [(size_t)MR*DM];
__device__ float g_ctx[(size_t)MR*DM];
__device__ float g_wb[(size_t)NB*SQ*SQ];   // pre-scaled relation bias

// ---------------- tf32 helpers ----------------
static __device__ __forceinline__ unsigned f2tf(float x){
    unsigned u; asm("cvt.rna.tf32.f32 %0, %1;" : "=r"(u) : "f"(x)); return u;
}
static __device__ __forceinline__ float f2tff(float x){ return __uint_as_float(f2tf(x)); }

static __device__ __forceinline__ void mma8(float* d,
        unsigned a0, unsigned a1, unsigned a2, unsigned a3,
        unsigned b0, unsigned b1){
    asm volatile("mma.sync.aligned.m16n8k8.row.col.f32.tf32.tf32.f32 "
        "{%0,%1,%2,%3}, {%4,%5,%6,%7}, {%8,%9}, {%0,%1,%2,%3};\n"
        : "+f"(d[0]), "+f"(d[1]), "+f"(d[2]), "+f"(d[3])
        : "r"(a0), "r"(a1), "r"(a2), "r"(a3), "r"(b0), "r"(b1));
}

#define CP_COMMIT() asm volatile("cp.async.commit_group;\n" ::: "memory")
#define CP_WAIT(n)  asm volatile("cp.async.wait_group %0;\n" :: "n"(n) : "memory")

// ---------------- LayerNorm (shared gamma/beta) ----------------
__global__ __launch_bounds__(256) void ln_kernel(
    const float* __restrict__ q, const float* __restrict__ k, const float* __restrict__ v,
    const float* __restrict__ gamma, const float* __restrict__ beta)
{
    int row = blockIdx.x;
    const float* src; float* dst;
    if (blockIdx.y == 0){ src = q; dst = g_qn; }
    else if (blockIdx.y == 1){ src = k; dst = g_kn; }
    else { src = v; dst = g_vn; }

    const float4 xv = ((const float4*)(src + (size_t)row*DM))[threadIdx.x];
    float s  = xv.x + xv.y + xv.z + xv.w;
    float sq = xv.x*xv.x + xv.y*xv.y + xv.z*xv.z + xv.w*xv.w;
    #pragma unroll
    for (int o = 16; o; o >>= 1){
        s  += __shfl_xor_sync(0xffffffffu, s,  o);
        sq += __shfl_xor_sync(0xffffffffu, sq, o);
    }
    __shared__ float rs[8], rq[8];
    int w = threadIdx.x >> 5, lane = threadIdx.x & 31;
    if (!lane){ rs[w] = s; rq[w] = sq; }
    __syncthreads();
    if (threadIdx.x == 0){
        float ts = 0.f, tq = 0.f;
        #pragma unroll
        for (int i = 0; i < 8; ++i){ ts += rs[i]; tq += rq[i]; }
        float mu  = ts * (1.f/DM);
        float var = tq * (1.f/DM) - mu*mu;
        rs[0] = mu; rq[0] = rsqrtf(var + 1e-5f);
    }
    __syncthreads();
    float mu = rs[0], rstd = rq[0];
    const float4 g4 = ((const float4*)gamma)[threadIdx.x];
    const float4 b4 = ((const float4*)beta )[threadIdx.x];
    float4 o;
    o.x = (xv.x - mu)*rstd*g4.x + b4.x;
    o.y = (xv.y - mu)*rstd*g4.y + b4.y;
    o.z = (xv.z - mu)*rstd*g4.z + b4.z;
    o.w = (xv.w - mu)*rstd*g4.w + b4.w;
    ((float4*)(dst + (size_t)row*DM))[threadIdx.x] = o;
}

// ---------------- relation bias ----------------
__global__ __launch_bounds__(256) void wbias_kernel(
    const float4* __restrict__ tr, const float* __restrict__ rtw, const float* __restrict__ rsc)
{
    float w0 = rtw[0], w1 = rtw[1], w2 = rtw[2], w3 = rtw[3];
    float mx = fmaxf(fmaxf(w0,w1), fmaxf(w2,w3));
    float e0 = expf(w0-mx), e1 = expf(w1-mx), e2 = expf(w2-mx), e3 = expf(w3-mx);
    float bs = 0.1f / (1.f + expf(-rsc[0]));
    float inv = bs / (e0+e1+e2+e3);
    float r0 = e0*inv, r1 = e1*inv, r2 = e2*inv, r3 = e3*inv;
    size_t i = (size_t)blockIdx.x*256 + threadIdx.x;
    float4 t = tr[i];
    g_wb[i] = t.x*r0 + t.y*r1 + t.z*r2 + t.w*r3;
}

// ---------------- TF32 GEMM: C[4096,1024] = A @ W^T + bias ----------------
__global__ __launch_bounds__(256,2) void gemm_tf32(
    const float* __restrict__ A, const float* __restrict__ W,
    const float* __restrict__ bias, float* __restrict__ C)
{
    __shared__ __align__(16) float As[2][128][20];
    __shared__ __align__(16) float Bs[2][128][20];
    const int tid = threadIdx.x, lane = tid & 31, wid = tid >> 5;
    const int wm = wid >> 1, wn = wid & 1;
    const int bm = blockIdx.y*128, bn = blockIdx.x*128;

    float acc[2][8][4];
    #pragma unroll
    for (int mt = 0; mt < 2; ++mt)
        #pragma unroll
        for (int nt = 0; nt < 8; ++nt)
            #pragma unroll
            for (int e = 0; e < 4; ++e) acc[mt][nt][e] = 0.f;

    const int lr = tid >> 2, lc = (tid & 3)*4;
    float4 ra[2], rb[2];

    #define FETCH(kt) do { \
        const float* Ap = A + (size_t)(bm+lr)*1024 + (kt)*16 + lc; \
        ra[0] = *(const float4*)Ap; ra[1] = *(const float4*)(Ap + (size_t)64*1024); \
        const float* Wp = W + (size_t)(bn+lr)*1024 + (kt)*16 + lc; \
        rb[0] = *(const float4*)Wp; rb[1] = *(const float4*)(Wp + (size_t)64*1024); \
    } while(0)
    #define STORE(st) do { \
        *(float4*)&As[st][lr   ][lc] = make_float4(f2tff(ra[0].x), f2tff(ra[0].y), f2tff(ra[0].z), f2tff(ra[0].w)); \
        *(float4*)&As[st][lr+64][lc] = make_float4(f2tff(ra[1].x), f2tff(ra[1].y), f2tff(ra[1].z), f2tff(ra[1].w)); \
        *(float4*)&Bs[st][lr   ][lc] = make_float4(f2tff(rb[0].x), f2tff(rb[0].y), f2tff(rb[0].z), f2tff(rb[0].w)); \
        *(float4*)&Bs[st][lr+64][lc] = make_float4(f2tff(rb[1].x), f2tff(rb[1].y), f2tff(rb[1].z), f2tff(rb[1].w)); \
    } while(0)

    FETCH(0); STORE(0); __syncthreads();

    for (int kt = 0; kt < 64; ++kt){
        const int cur = kt & 1;
        if (kt < 63) FETCH(kt+1);
        #pragma unroll
        for (int ks = 0; ks < 2; ++ks){
            const int k0 = ks*8 + (lane & 3);
            unsigned af[2][4], bf[8][2];
            #pragma unroll
            for (int mt = 0; mt < 2; ++mt){
                int r = wm*32 + mt*16 + (lane >> 2);
                af[mt][0] = __float_as_uint(As[cur][r  ][k0  ]);
                af[mt][1] = __float_as_uint(As[cur][r+8][k0  ]);
                af[mt][2] = __float_as_uint(As[cur][r  ][k0+4]);
                af[mt][3] = __float_as_uint(As[cur][r+8][k0+4]);
            }
            #pragma unroll
            for (int nt = 0; nt < 8; ++nt){
                int n = wn*64 + nt*8 + (lane >> 2);
                bf[nt][0] = __float_as_uint(Bs[cur][n][k0  ]);
                bf[nt][1] = __float_as_uint(Bs[cur][n][k0+4]);
            }
            #pragma unroll
            for (int mt = 0; mt < 2; ++mt)
                #pragma unroll
                for (int nt = 0; nt < 8; ++nt)
                    mma8(acc[mt][nt], af[mt][0], af[mt][1], af[mt][2], af[mt][3],
                         bf[nt][0], bf[nt][1]);
        }
        if (kt < 63) STORE(cur ^ 1);
        __syncthreads();
    }
    #undef FETCH
    #undef STORE

    #pragma unroll
    for (int mt = 0; mt < 2; ++mt)
        #pragma unroll
        for (int nt = 0; nt < 8; ++nt)
            #pragma unroll
            for (int e = 0; e < 4; ++e){
                int r = bm + wm*32 + mt*16 + (lane >> 2) + ((e >> 1) << 3);
                int c = bn + wn*64 + nt*8 + (lane & 3)*2 + (e & 1);
                C[(size_t)r*1024 + c] = acc[mt][nt][e] + bias[c];
            }
}

// ---------------- fused attention (pipelined, 512 threads) ----------------
// smem: scores 16x2052, KV double-buffer 2x128x68, Qs 16x72 (reused as k-split red)
#define AT_SS 2052
#define KVP   68
#define KVSZ  (128*KVP)

static __device__ __forceinline__ void cp_tile(float* dstbuf, const float* src_base, int tid){
    #pragma unroll
    for (int j = 0; j < 4; ++j){
        int idx = tid + j*512;
        int r = idx >> 4, c = (idx & 15)*4;
        uint32_t daddr = (uint32_t)__cvta_generic_to_shared(dstbuf + r*KVP + c);
        const float* s = src_base + (size_t)r*DM + c;
        asm volatile("cp.async.cg.shared.global [%0], [%1], 16;\n" :: "r"(daddr), "l"(s) : "memory");
    }
}

__global__ __launch_bounds__(512) void attn_kernel(
    const int* __restrict__ mask, float* __restrict__ attnw)
{
    extern __shared__ float smem[];
    float* sc = smem;                 // [16][AT_SS]
    float* KV = smem + 16*AT_SS;      // [2][128][KVP]
    float* Qs = KV + 2*KVSZ;          // [16][72], reused as reduction buf [16][64]

    const int b = blockIdx.z, h = blockIdx.y, q0 = blockIdx.x*16;
    const int tid = threadIdx.x, lane = tid & 31, w = tid >> 5;

    const float* Kbase = g_k + ((size_t)b*SQ)*DM + h*HD;
    const float* Vbase = g_v + ((size_t)b*SQ)*DM + h*HD;

    // load + tf32-round Q tile (16 x 64)
    if (tid < 256){
        int r = tid >> 4, c4 = tid & 15;
        const float* qb = g_q + ((size_t)(b*SQ + q0 + r))*DM + h*HD + c4*4;
        float4 v = *(const float4*)qb;
        *(float4*)&Qs[r*72 + c4*4] =
            make_float4(f2tff(v.x), f2tff(v.y), f2tff(v.z), f2tff(v.w));
    }

    // prefetch K tiles 0,1
    cp_tile(KV,        Kbase,              tid); CP_COMMIT();
    cp_tile(KV + KVSZ, Kbase + 128*DM,     tid); CP_COMMIT();
    __syncthreads();

    // preload Q fragments (const across all tiles)
    unsigned qa[8][4];
    {
        const int ar = lane >> 2;
        #pragma unroll
        for (int ks = 0; ks < 8; ++ks){
            int ak = ks*8 + (lane & 3);
            qa[ks][0] = __float_as_uint(Qs[ ar   *72 + ak  ]);
            qa[ks][1] = __float_as_uint(Qs[(ar+8)*72 + ak  ]);
            qa[ks][2] = __float_as_uint(Qs[ ar   *72 + ak+4]);
            qa[ks][3] = __float_as_uint(Qs[(ar+8)*72 + ak+4]);
        }
    }

    // ---- Phase 1: raw scores = QK^T into smem ----
    for (int t = 0; t < 16; ++t){
        if (t < 15) CP_WAIT(1); else CP_WAIT(0);
        __syncthreads();
        {
            const float* B = KV + (t & 1)*KVSZ;
            const float* Bp = B + (w*8 + (lane >> 2))*KVP + (lane & 3);
            float acc[4] = {0.f, 0.f, 0.f, 0.f};
            #pragma unroll
            for (int ks = 0; ks < 8; ++ks){
                unsigned b0 = f2tf(Bp[ks*8    ]);
                unsigned b1 = f2tf(Bp[ks*8 + 4]);
                mma8(acc, qa[ks][0], qa[ks][1], qa[ks][2], qa[ks][3], b0, b1);
            }
            const int r0 = lane >> 2;
            const int c  = t*128 + w*8 + (lane & 3)*2;
            *(float2*)&sc[ r0   *AT_SS + c] = make_float2(acc[0], acc[1]);
            *(float2*)&sc[(r0+8)*AT_SS + c] = make_float2(acc[2], acc[3]);
        }
        __syncthreads();
        if (t + 2 < 16){
            cp_tile(KV + (t & 1)*KVSZ, Kbase + (size_t)(t+2)*128*DM, tid);
            CP_COMMIT();
        }
    }

    // prefetch V tiles 0,1 (overlaps with softmax)
    cp_tile(KV,        Vbase,          tid); CP_COMMIT();
    cp_tile(KV + KVSZ, Vbase + 128*DM, tid); CP_COMMIT();

    // ---- Phase 2: bias + mask + softmax + stream attn_weights (1 warp per row) ----
    {
        const int rr = w;
        float4* s4 = (float4*)(sc + rr*AT_SS);
        const float4* wb4 = (const float4*)(g_wb + ((size_t)(b*SQ + q0 + rr))*SQ);
        const int4*   mk4 = (const int4*)(mask + (size_t)b*SQ);
        float m = -1e30f;
        for (int i = lane; i < 512; i += 32){
            float4 s = s4[i]; float4 wv = wb4[i]; int4 mk = mk4[i];
            s.x = mk.x ? fmaf(s.x, 0.125f, wv.x) : -1e9f;
            s.y = mk.y ? fmaf(s.y, 0.125f, wv.y) : -1e9f;
            s.z = mk.z ? fmaf(s.z, 0.125f, wv.z) : -1e9f;
            s.w = mk.w ? fmaf(s.w, 0.125f, wv.w) : -1e9f;
            m = fmaxf(m, fmaxf(fmaxf(s.x, s.y), fmaxf(s.z, s.w)));
            s4[i] = s;
        }
        #pragma unroll
        for (int o = 16; o; o >>= 1) m = fmaxf(m, __shfl_xor_sync(0xffffffffu, m, o));
        float sum = 0.f;
        for (int i = lane; i < 512; i += 32){
            float4 s = s4[i];
            s.x = __expf(s.x - m); s.y = __expf(s.y - m);
            s.z = __expf(s.z - m); s.w = __expf(s.w - m);
            sum += s.x + s.y + s.z + s.w;
            s4[i] = s;
        }
        #pragma unroll
        for (int o = 16; o; o >>= 1) sum += __shfl_xor_sync(0xffffffffu, sum, o);
        float inv = 1.f / sum;
        float4* o4 = (float4*)(attnw + (((size_t)(b*NH + h)*SQ + q0 + rr))*SQ);
        for (int i = lane; i < 512; i += 32){
            float4 p = s4[i];
            p.x *= inv; p.y *= inv; p.z *= inv; p.w *= inv;
            s4[i] = p; o4[i] = p;
        }
    }
    __syncthreads();

    // ---- Phase 3: ctx = P @ V, k-split across warp halves ----
    float oacc[4] = {0.f, 0.f, 0.f, 0.f};
    const int nw = w & 7, kh = w >> 3;
    for (int t = 0; t < 16; ++t){
        if (t < 15) CP_WAIT(1); else CP_WAIT(0);
        __syncthreads();
        if ((t & 1) == kh){
            const float* B = KV + (t & 1)*KVSZ;
            const int ar = lane >> 2;
            const int bn = nw*8 + (lane >> 2);
            #pragma unroll
            for (int ks = 0; ks < 16; ++ks){
                int kg = t*128 + ks*8 + (lane & 3);
                unsigned a0 = f2tf(sc[ ar   *AT_SS + kg  ]);
                unsigned a1 = f2tf(sc[(ar+8)*AT_SS + kg  ]);
                unsigned a2 = f2tf(sc[ ar   *AT_SS + kg+4]);
                unsigned a3 = f2tf(sc[(ar+8)*AT_SS + kg+4]);
                unsigned b0 = f2tf(B[(ks*8 + (lane & 3)    )*KVP + bn]);
                unsigned b1 = f2tf(B[(ks*8 + (lane & 3) + 4)*KVP + bn]);
                mma8(oacc, a0, a1, a2, a3, b0, b1);
            }
        }
        __syncthreads();
        if (t + 2 < 16){
            cp_tile(KV + (t & 1)*KVSZ, Vbase + (size_t)(t+2)*128*DM, tid);
            CP_COMMIT();
        }
    }

    // k-split reduction via smem (reuse Qs as [16][64])
    float* red = Qs;
    {
        const int r0 = lane >> 2, c = nw*8 + (lane & 3)*2;
        if (kh == 1){
            *(float2*)&red[ r0   *64 + c] = make_float2(oacc[0], oacc[1]);
            *(float2*)&red[(r0+8)*64 + c] = make_float2(oacc[2], oacc[3]);
        }
        __syncthreads();
        if (kh == 0){
            float2 p0 = *(float2*)&red[ r0   *64 + c];
            float2 p1 = *(float2*)&red[(r0+8)*64 + c];
            float* o0 = g_ctx + ((size_t)(b*SQ + q0 + r0   ))*DM + h*HD + c;
            float* o1 = g_ctx + ((size_t)(b*SQ + q0 + r0+8 ))*DM + h*HD + c;
            *(float2*)o0 = make_float2(oacc[0] + p0.x, oacc[1] + p0.y);
            *(float2*)o1 = make_float2(oacc[2] + p1.x, oacc[3] + p1.y);
        }
    }
}

// ---------------- launcher ----------------
extern "C" void kernel_launch(void* const* d_in, const int* in_sizes, int n_in,
                              void* d_out, int out_size)
{
    const float* q     = (const float*)d_in[0];
    const float* k     = (const float*)d_in[1];
    const float* v     = (const float*)d_in[2];
    const int*   mask  = (const int*)  d_in[3];
    const float* tagr  = (const float*)d_in[4];
    const float* gamma = (const float*)d_in[5];
    const float* beta  = (const float*)d_in[6];
    const float* Wq    = (const float*)d_in[7];
    const float* bq    = (const float*)d_in[8];
    const float* Wk    = (const float*)d_in[9];
    const float* bk    = (const float*)d_in[10];
    const float* Wv    = (const float*)d_in[11];
    const float* bv    = (const float*)d_in[12];
    const float* Wo    = (const float*)d_in[13];
    const float* bo    = (const float*)d_in[14];
    const float* rtw   = (const float*)d_in[15];
    const float* rsc   = (const float*)d_in[16];

    float* out   = (float*)d_out;
    float* attnw = out + (size_t)MR*DM;

    float *p_qn, *p_kn, *p_vn, *p_q, *p_k, *p_v, *p_ctx;
    cudaGetSymbolAddress((void**)&p_qn, g_qn);
    cudaGetSymbolAddress((void**)&p_kn, g_kn);
    cudaGetSymbolAddress((void**)&p_vn, g_vn);
    cudaGetSymbolAddress((void**)&p_q,  g_q);
    cudaGetSymbolAddress((void**)&p_k,  g_k);
    cudaGetSymbolAddress((void**)&p_v,  g_v);
    cudaGetSymbolAddress((void**)&p_ctx, g_ctx);

    ln_kernel<<<dim3(MR, 3), 256>>>(q, k, v, gamma, beta);
    wbias_kernel<<<(NB*SQ*SQ)/256, 256>>>((const float4*)tagr, rtw, rsc);

    gemm_tf32<<<dim3(8, 32), 256>>>(p_qn, Wq, bq, p_q);
    gemm_tf32<<<dim3(8, 32), 256>>>(p_kn, Wk, bk, p_k);
    gemm_tf32<<<dim3(8, 32), 256>>>(p_vn, Wv, bv, p_v);

    const int shbytes = (16*AT_SS + 2*KVSZ + 16*72) * 4;
    cudaFuncSetAttribute(attn_kernel, cudaFuncAttributeMaxDynamicSharedMemorySize, 220*1024);
    attn_kernel<<<dim3(SQ/16, NH, NB), 512, shbytes>>>(mask, attnw);

    gemm_tf32<<<dim3(8, 32), 256>>>(p_ctx, Wo, bo, out);
}

// round 8
// speedup vs baseline: 2.3416x; 1.1236x over previous
#include <cuda_runtime.h>
#include <math.h>
#include <stdint.h>

#define DM 1024
#define NH 16
#define HD 64
#define NB 2
#define SQ 2048
#define MR (NB*SQ)   // 4096 token rows

// ---------------- scratch (device globals: allocation-free) ----------------
__device__ float g_qn[(size_t)MR*DM];
__device__ float g_kn[(size_t)MR*DM];
__device__ float g_vn[(size_t)MR*DM];
__device__ float g_q [(size_t)MR*DM];
__device__ float g_k [(size_t)MR*DM];
__device__ float g_v [(size_t)MR*DM];
__device__ float g_ctx[(size_t)MR*DM];
__device__ float g_wb[(size_t)NB*SQ*SQ];   // pre-scaled relation bias

// ---------------- tf32 helpers ----------------
static __device__ __forceinline__ unsigned f2tf(float x){
    unsigned u; asm("cvt.rna.tf32.f32 %0, %1;" : "=r"(u) : "f"(x)); return u;
}
static __device__ __forceinline__ float f2tff(float x){ return __uint_as_float(f2tf(x)); }

static __device__ __forceinline__ void mma8(float* d,
        unsigned a0, unsigned a1, unsigned a2, unsigned a3,
        unsigned b0, unsigned b1){
    asm volatile("mma.sync.aligned.m16n8k8.row.col.f32.tf32.tf32.f32 "
        "{%0,%1,%2,%3}, {%4,%5,%6,%7}, {%8,%9}, {%0,%1,%2,%3};\n"
        : "+f"(d[0]), "+f"(d[1]), "+f"(d[2]), "+f"(d[3])
        : "r"(a0), "r"(a1), "r"(a2), "r"(a3), "r"(b0), "r"(b1));
}

#define CP_COMMIT() asm volatile("cp.async.commit_group;\n" ::: "memory")
#define CP_WAIT(n)  asm volatile("cp.async.wait_group %0;\n" :: "n"(n) : "memory")

// ---------------- LayerNorm (shared gamma/beta) ----------------
__global__ __launch_bounds__(256) void ln_kernel(
    const float* __restrict__ q, const float* __restrict__ k, const float* __restrict__ v,
    const float* __restrict__ gamma, const float* __restrict__ beta)
{
    int row = blockIdx.x;
    const float* src; float* dst;
    if (blockIdx.y == 0){ src = q; dst = g_qn; }
    else if (blockIdx.y == 1){ src = k; dst = g_kn; }
    else { src = v; dst = g_vn; }

    const float4 xv = ((const float4*)(src + (size_t)row*DM))[threadIdx.x];
    float s  = xv.x + xv.y + xv.z + xv.w;
    float sq = xv.x*xv.x + xv.y*xv.y + xv.z*xv.z + xv.w*xv.w;
    #pragma unroll
    for (int o = 16; o; o >>= 1){
        s  += __shfl_xor_sync(0xffffffffu, s,  o);
        sq += __shfl_xor_sync(0xffffffffu, sq, o);
    }
    __shared__ float rs[8], rq[8];
    int w = threadIdx.x >> 5, lane = threadIdx.x & 31;
    if (!lane){ rs[w] = s; rq[w] = sq; }
    __syncthreads();
    if (threadIdx.x == 0){
        float ts = 0.f, tq = 0.f;
        #pragma unroll
        for (int i = 0; i < 8; ++i){ ts += rs[i]; tq += rq[i]; }
        float mu  = ts * (1.f/DM);
        float var = tq * (1.f/DM) - mu*mu;
        rs[0] = mu; rq[0] = rsqrtf(var + 1e-5f);
    }
    __syncthreads();
    float mu = rs[0], rstd = rq[0];
    const float4 g4 = ((const float4*)gamma)[threadIdx.x];
    const float4 b4 = ((const float4*)beta )[threadIdx.x];
    float4 o;
    o.x = (xv.x - mu)*rstd*g4.x + b4.x;
    o.y = (xv.y - mu)*rstd*g4.y + b4.y;
    o.z = (xv.z - mu)*rstd*g4.z + b4.z;
    o.w = (xv.w - mu)*rstd*g4.w + b4.w;
    ((float4*)(dst + (size_t)row*DM))[threadIdx.x] = o;
}

// ---------------- relation bias ----------------
__global__ __launch_bounds__(256) void wbias_kernel(
    const float4* __restrict__ tr, const float* __restrict__ rtw, const float* __restrict__ rsc)
{
    float w0 = rtw[0], w1 = rtw[1], w2 = rtw[2], w3 = rtw[3];
    float mx = fmaxf(fmaxf(w0,w1), fmaxf(w2,w3));
    float e0 = expf(w0-mx), e1 = expf(w1-mx), e2 = expf(w2-mx), e3 = expf(w3-mx);
    float bs = 0.1f / (1.f + expf(-rsc[0]));
    float inv = bs / (e0+e1+e2+e3);
    float r0 = e0*inv, r1 = e1*inv, r2 = e2*inv, r3 = e3*inv;
    size_t i = (size_t)blockIdx.x*256 + threadIdx.x;
    float4 t = tr[i];
    g_wb[i] = t.x*r0 + t.y*r1 + t.z*r2 + t.w*r3;
}

// ---------------- TF32 GEMM: C[4096,1024] = A @ W^T + bias ----------------
__global__ __launch_bounds__(256,2) void gemm_tf32(
    const float* __restrict__ A, const float* __restrict__ W,
    const float* __restrict__ bias, float* __restrict__ C)
{
    __shared__ __align__(16) float As[2][128][20];
    __shared__ __align__(16) float Bs[2][128][20];
    const int tid = threadIdx.x, lane = tid & 31, wid = tid >> 5;
    const int wm = wid >> 1, wn = wid & 1;
    const int bm = blockIdx.y*128, bn = blockIdx.x*128;

    float acc[2][8][4];
    #pragma unroll
    for (int mt = 0; mt < 2; ++mt)
        #pragma unroll
        for (int nt = 0; nt < 8; ++nt)
            #pragma unroll
            for (int e = 0; e < 4; ++e) acc[mt][nt][e] = 0.f;

    const int lr = tid >> 2, lc = (tid & 3)*4;
    float4 ra[2], rb[2];

    #define FETCH(kt) do { \
        const float* Ap = A + (size_t)(bm+lr)*1024 + (kt)*16 + lc; \
        ra[0] = *(const float4*)Ap; ra[1] = *(const float4*)(Ap + (size_t)64*1024); \
        const float* Wp = W + (size_t)(bn+lr)*1024 + (kt)*16 + lc; \
        rb[0] = *(const float4*)Wp; rb[1] = *(const float4*)(Wp + (size_t)64*1024); \
    } while(0)
    #define STORE(st) do { \
        *(float4*)&As[st][lr   ][lc] = make_float4(f2tff(ra[0].x), f2tff(ra[0].y), f2tff(ra[0].z), f2tff(ra[0].w)); \
        *(float4*)&As[st][lr+64][lc] = make_float4(f2tff(ra[1].x), f2tff(ra[1].y), f2tff(ra[1].z), f2tff(ra[1].w)); \
        *(float4*)&Bs[st][lr   ][lc] = make_float4(f2tff(rb[0].x), f2tff(rb[0].y), f2tff(rb[0].z), f2tff(rb[0].w)); \
        *(float4*)&Bs[st][lr+64][lc] = make_float4(f2tff(rb[1].x), f2tff(rb[1].y), f2tff(rb[1].z), f2tff(rb[1].w)); \
    } while(0)

    FETCH(0); STORE(0); __syncthreads();

    for (int kt = 0; kt < 64; ++kt){
        const int cur = kt & 1;
        if (kt < 63) FETCH(kt+1);
        #pragma unroll
        for (int ks = 0; ks < 2; ++ks){
            const int k0 = ks*8 + (lane & 3);
            unsigned af[2][4], bf[8][2];
            #pragma unroll
            for (int mt = 0; mt < 2; ++mt){
                int r = wm*32 + mt*16 + (lane >> 2);
                af[mt][0] = __float_as_uint(As[cur][r  ][k0  ]);
                af[mt][1] = __float_as_uint(As[cur][r+8][k0  ]);
                af[mt][2] = __float_as_uint(As[cur][r  ][k0+4]);
                af[mt][3] = __float_as_uint(As[cur][r+8][k0+4]);
            }
            #pragma unroll
            for (int nt = 0; nt < 8; ++nt){
                int n = wn*64 + nt*8 + (lane >> 2);
                bf[nt][0] = __float_as_uint(Bs[cur][n][k0  ]);
                bf[nt][1] = __float_as_uint(Bs[cur][n][k0+4]);
            }
            #pragma unroll
            for (int mt = 0; mt < 2; ++mt)
                #pragma unroll
                for (int nt = 0; nt < 8; ++nt)
                    mma8(acc[mt][nt], af[mt][0], af[mt][1], af[mt][2], af[mt][3],
                         bf[nt][0], bf[nt][1]);
        }
        if (kt < 63) STORE(cur ^ 1);
        __syncthreads();
    }
    #undef FETCH
    #undef STORE

    #pragma unroll
    for (int mt = 0; mt < 2; ++mt)
        #pragma unroll
        for (int nt = 0; nt < 8; ++nt)
            #pragma unroll
            for (int e = 0; e < 4; ++e){
                int r = bm + wm*32 + mt*16 + (lane >> 2) + ((e >> 1) << 3);
                int c = bn + wn*64 + nt*8 + (lane & 3)*2 + (e & 1);
                C[(size_t)r*1024 + c] = acc[mt][nt][e] + bias[c];
            }
}

// ---------------- fused attention: scores fully register-resident ----------------
// 512 threads, 16 warps. Warp w owns key-columns [w*8, w*8+8) of every 128-key tile.
// Per-lane score storage: s[16][4] = the warp's C fragments for all 16 tiles.
#define KVP   68
#define KVSZ  (128*KVP)

static __device__ __forceinline__ void cp_tile(float* dstbuf, const float* src_base, int tid){
    #pragma unroll
    for (int j = 0; j < 4; ++j){
        int idx = tid + j*512;
        int r = idx >> 4, c = (idx & 15)*4;
        uint32_t daddr = (uint32_t)__cvta_generic_to_shared(dstbuf + r*KVP + c);
        const float* s = src_base + (size_t)r*DM + c;
        asm volatile("cp.async.cg.shared.global [%0], [%1], 16;\n" :: "r"(daddr), "l"(s) : "memory");
    }
}

__global__ __launch_bounds__(512) void attn_kernel(
    const int* __restrict__ mask, float* __restrict__ attnw)
{
    extern __shared__ float smem[];
    float* KV  = smem;                 // [2][128][KVP]  = 69.6KB
    float* Qs  = KV + 2*KVSZ;          // [16][72]
    float* red = Qs + 16*72;           // [8][1024] O-reduction = 32KB
    float* mx  = red + 8*1024;         // [16][16]
    float* sm  = mx + 256;             // [16][16]

    const int b = blockIdx.z, h = blockIdx.y, q0 = blockIdx.x*16;
    const int tid = threadIdx.x, lane = tid & 31, w = tid >> 5;
    const int u = lane & 3, r0 = lane >> 2;

    const float* Kbase = g_k + ((size_t)b*SQ)*DM + h*HD;
    const float* Vbase = g_v + ((size_t)b*SQ)*DM + h*HD;

    // load + tf32-round Q tile (16 x 64)
    if (tid < 256){
        int r = tid >> 4, c4 = tid & 15;
        const float* qb = g_q + ((size_t)(b*SQ + q0 + r))*DM + h*HD + c4*4;
        float4 v = *(const float4*)qb;
        *(float4*)&Qs[r*72 + c4*4] =
            make_float4(f2tff(v.x), f2tff(v.y), f2tff(v.z), f2tff(v.w));
    }

    // prefetch K tiles 0,1
    cp_tile(KV,        Kbase,          tid); CP_COMMIT();
    cp_tile(KV + KVSZ, Kbase + 128*DM, tid); CP_COMMIT();
    __syncthreads();

    // preload Q fragments (live through phase 1 only)
    unsigned qa[8][4];
    #pragma unroll
    for (int ks = 0; ks < 8; ++ks){
        int ak = ks*8 + u;
        qa[ks][0] = __float_as_uint(Qs[ r0   *72 + ak  ]);
        qa[ks][1] = __float_as_uint(Qs[(r0+8)*72 + ak  ]);
        qa[ks][2] = __float_as_uint(Qs[ r0   *72 + ak+4]);
        qa[ks][3] = __float_as_uint(Qs[(r0+8)*72 + ak+4]);
    }

    float s[16][4];   // register-resident score slice

    const float* wbr0 = g_wb + ((size_t)(b*SQ + q0 + r0    ))*SQ;
    const float* wbr1 = g_wb + ((size_t)(b*SQ + q0 + r0 + 8))*SQ;
    const int*   mkb  = mask + (size_t)b*SQ;

    // ---- Phase 1: scores = QK^T/8 + bias, masked -> registers ----
    #pragma unroll
    for (int t = 0; t < 16; ++t){
        if (t < 15) CP_WAIT(1); else CP_WAIT(0);
        __syncthreads();
        {
            const float* Bp = KV + (t & 1)*KVSZ + (w*8 + r0)*KVP + u;
            float acc[4] = {0.f, 0.f, 0.f, 0.f};
            #pragma unroll
            for (int ks = 0; ks < 8; ++ks){
                unsigned b0 = f2tf(Bp[ks*8    ]);
                unsigned b1 = f2tf(Bp[ks*8 + 4]);
                mma8(acc, qa[ks][0], qa[ks][1], qa[ks][2], qa[ks][3], b0, b1);
            }
            const int cg = t*128 + w*8 + 2*u;
            float2 w0 = *(const float2*)(wbr0 + cg);
            float2 w1 = *(const float2*)(wbr1 + cg);
            int2   mk = *(const int2*)(mkb + cg);
            s[t][0] = mk.x ? fmaf(acc[0], 0.125f, w0.x) : -1e9f;
            s[t][1] = mk.y ? fmaf(acc[1], 0.125f, w0.y) : -1e9f;
            s[t][2] = mk.x ? fmaf(acc[2], 0.125f, w1.x) : -1e9f;
            s[t][3] = mk.y ? fmaf(acc[3], 0.125f, w1.y) : -1e9f;
        }
        __syncthreads();
        if (t + 2 < 16){
            cp_tile(KV + (t & 1)*KVSZ, Kbase + (size_t)(t+2)*128*DM, tid);
            CP_COMMIT();
        }
    }

    // all warps done with K buffers -> safe to prefetch V tiles 0,1
    __syncthreads();
    cp_tile(KV,        Vbase,          tid); CP_COMMIT();
    cp_tile(KV + KVSZ, Vbase + 128*DM, tid); CP_COMMIT();

    // ---- Phase 2: softmax over registers + stream attn_weights ----
    {
        float lm0 = -1e30f, lm1 = -1e30f;
        #pragma unroll
        for (int t = 0; t < 16; ++t){
            lm0 = fmaxf(lm0, fmaxf(s[t][0], s[t][1]));
            lm1 = fmaxf(lm1, fmaxf(s[t][2], s[t][3]));
        }
        lm0 = fmaxf(lm0, __shfl_xor_sync(0xffffffffu, lm0, 1));
        lm0 = fmaxf(lm0, __shfl_xor_sync(0xffffffffu, lm0, 2));
        lm1 = fmaxf(lm1, __shfl_xor_sync(0xffffffffu, lm1, 1));
        lm1 = fmaxf(lm1, __shfl_xor_sync(0xffffffffu, lm1, 2));
        if (u == 0){ mx[w*16 + r0] = lm0; mx[w*16 + r0 + 8] = lm1; }
        __syncthreads();
        float M0 = -1e30f, M1 = -1e30f;
        #pragma unroll
        for (int i = 0; i < 16; ++i){
            M0 = fmaxf(M0, mx[i*16 + r0]);
            M1 = fmaxf(M1, mx[i*16 + r0 + 8]);
        }
        float s0 = 0.f, s1 = 0.f;
        #pragma unroll
        for (int t = 0; t < 16; ++t){
            s[t][0] = __expf(s[t][0] - M0);
            s[t][1] = __expf(s[t][1] - M0);
            s[t][2] = __expf(s[t][2] - M1);
            s[t][3] = __expf(s[t][3] - M1);
            s0 += s[t][0] + s[t][1];
            s1 += s[t][2] + s[t][3];
        }
        s0 += __shfl_xor_sync(0xffffffffu, s0, 1);
        s0 += __shfl_xor_sync(0xffffffffu, s0, 2);
        s1 += __shfl_xor_sync(0xffffffffu, s1, 1);
        s1 += __shfl_xor_sync(0xffffffffu, s1, 2);
        if (u == 0){ sm[w*16 + r0] = s0; sm[w*16 + r0 + 8] = s1; }
        __syncthreads();
        float S0 = 0.f, S1 = 0.f;
        #pragma unroll
        for (int i = 0; i < 16; ++i){
            S0 += sm[i*16 + r0];
            S1 += sm[i*16 + r0 + 8];
        }
        float i0 = 1.f / S0, i1 = 1.f / S1;
        float* o0 = attnw + (((size_t)(b*NH + h)*SQ + q0 + r0    ))*SQ + w*8 + 2*u;
        float* o1 = attnw + (((size_t)(b*NH + h)*SQ + q0 + r0 + 8))*SQ + w*8 + 2*u;
        #pragma unroll
        for (int t = 0; t < 16; ++t){
            s[t][0] *= i0; s[t][1] *= i0;
            s[t][2] *= i1; s[t][3] *= i1;
            *(float2*)(o0 + t*128) = make_float2(s[t][0], s[t][1]);
            *(float2*)(o1 + t*128) = make_float2(s[t][2], s[t][3]);
        }
    }

    // ---- Phase 3: partial O = P_slice @ V_slice per warp (k = warp's columns) ----
    float oacc[8][4];
    #pragma unroll
    for (int nb = 0; nb < 8; ++nb)
        #pragma unroll
        for (int e = 0; e < 4; ++e) oacc[nb][e] = 0.f;

    const int src1 = (lane & ~3) | (u >> 1);
    const int src2 = src1 + 2;

    #pragma unroll
    for (int t = 0; t < 16; ++t){
        if (t < 15) CP_WAIT(1); else CP_WAIT(0);
        __syncthreads();
        {
            // C-layout -> A-layout: gather cols u, u+4 of the warp's 8-col block
            float t00 = __shfl_sync(0xffffffffu, s[t][0], src1);
            float t01 = __shfl_sync(0xffffffffu, s[t][1], src1);
            float t10 = __shfl_sync(0xffffffffu, s[t][2], src1);
            float t11 = __shfl_sync(0xffffffffu, s[t][3], src1);
            float v00 = __shfl_sync(0xffffffffu, s[t][0], src2);
            float v01 = __shfl_sync(0xffffffffu, s[t][1], src2);
            float v10 = __shfl_sync(0xffffffffu, s[t][2], src2);
            float v11 = __shfl_sync(0xffffffffu, s[t][3], src2);
            unsigned a0 = f2tf((u & 1) ? t01 : t00);
            unsigned a1 = f2tf((u & 1) ? t11 : t10);
            unsigned a2 = f2tf((u & 1) ? v01 : v00);
            unsigned a3 = f2tf((u & 1) ? v11 : v10);

            const float* Vt = KV + (t & 1)*KVSZ;
            const float* Bp0 = Vt + (w*8 + u    )*KVP + r0;
            const float* Bp1 = Vt + (w*8 + u + 4)*KVP + r0;
            #pragma unroll
            for (int nb = 0; nb < 8; ++nb){
                unsigned b0 = f2tf(Bp0[nb*8]);
                unsigned b1 = f2tf(Bp1[nb*8]);
                mma8(oacc[nb], a0, a1, a2, a3, b0, b1);
            }
        }
        __syncthreads();
        if (t + 2 < 16){
            cp_tile(KV + (t & 1)*KVSZ, Vbase + (size_t)(t+2)*128*DM, tid);
            CP_COMMIT();
        }
    }

    // ---- tree-reduce O over 16 warps ----
    #pragma unroll
    for (int half = 8; half >= 1; half >>= 1){
        if (w >= half && w < 2*half){
            float* dst = red + (w - half)*1024 + lane*4;
            #pragma unroll
            for (int nb = 0; nb < 8; ++nb)
                *(float4*)(dst + nb*128) =
                    make_float4(oacc[nb][0], oacc[nb][1], oacc[nb][2], oacc[nb][3]);
        }
        __syncthreads();
        if (w < half){
            const float* srcp = red + w*1024 + lane*4;
            #pragma unroll
            for (int nb = 0; nb < 8; ++nb){
                float4 p = *(const float4*)(srcp + nb*128);
                oacc[nb][0] += p.x; oacc[nb][1] += p.y;
                oacc[nb][2] += p.z; oacc[nb][3] += p.w;
            }
        }
        __syncthreads();
    }

    if (w == 0){
        float* c0 = g_ctx + ((size_t)(b*SQ + q0 + r0    ))*DM + h*HD + 2*u;
        float* c1 = g_ctx + ((size_t)(b*SQ + q0 + r0 + 8))*DM + h*HD + 2*u;
        #pragma unroll
        for (int nb = 0; nb < 8; ++nb){
            *(float2*)(c0 + nb*8) = make_float2(oacc[nb][0], oacc[nb][1]);
            *(float2*)(c1 + nb*8) = make_float2(oacc[nb][2], oacc[nb][3]);
        }
    }
}

// ---------------- launcher ----------------
extern "C" void kernel_launch(void* const* d_in, const int* in_sizes, int n_in,
                              void* d_out, int out_size)
{
    const float* q     = (const float*)d_in[0];
    const float* k     = (const float*)d_in[1];
    const float* v     = (const float*)d_in[2];
    const int*   mask  = (const int*)  d_in[3];
    const float* tagr  = (const float*)d_in[4];
    const float* gamma = (const float*)d_in[5];
    const float* beta  = (const float*)d_in[6];
    const float* Wq    = (const float*)d_in[7];
    const float* bq    = (const float*)d_in[8];
    const float* Wk    = (const float*)d_in[9];
    const float* bk    = (const float*)d_in[10];
    const float* Wv    = (const float*)d_in[11];
    const float* bv    = (const float*)d_in[12];
    const float* Wo    = (const float*)d_in[13];
    const float* bo    = (const float*)d_in[14];
    const float* rtw   = (const float*)d_in[15];
    const float* rsc   = (const float*)d_in[16];

    float* out   = (float*)d_out;
    float* attnw = out + (size_t)MR*DM;

    float *p_qn, *p_kn, *p_vn, *p_q, *p_k, *p_v, *p_ctx;
    cudaGetSymbolAddress((void**)&p_qn, g_qn);
    cudaGetSymbolAddress((void**)&p_kn, g_kn);
    cudaGetSymbolAddress((void**)&p_vn, g_vn);
    cudaGetSymbolAddress((void**)&p_q,  g_q);
    cudaGetSymbolAddress((void**)&p_k,  g_k);
    cudaGetSymbolAddress((void**)&p_v,  g_v);
    cudaGetSymbolAddress((void**)&p_ctx, g_ctx);

    ln_kernel<<<dim3(MR, 3), 256>>>(q, k, v, gamma, beta);
    wbias_kernel<<<(NB*SQ*SQ)/256, 256>>>((const float4*)tagr, rtw, rsc);

    gemm_tf32<<<dim3(8, 32), 256>>>(p_qn, Wq, bq, p_q);
    gemm_tf32<<<dim3(8, 32), 256>>>(p_kn, Wk, bk, p_k);
    gemm_tf32<<<dim3(8, 32), 256>>>(p_vn, Wv, bv, p_v);

    // smem: 2*KVSZ + Qs(16*72) + red(8*1024) + mx(256) + sm(256)
    const int shbytes = (2*KVSZ + 16*72 + 8*1024 + 256 + 256) * 4;
    cudaFuncSetAttribute(attn_kernel, cudaFuncAttributeMaxDynamicSharedMemorySize, 160*1024);
    attn_kernel<<<dim3(SQ/16, NH, NB), 512, shbytes>>>(mask, attnw);

    gemm_tf32<<<dim3(8, 32), 256>>>(p_ctx, Wo, bo, out);
}

// round 9
// speedup vs baseline: 2.4155x; 1.0316x over previous
#include <cuda_runtime.h>
#include <math.h>
#include <stdint.h>

#define DM 1024
#define NH 16
#define HD 64
#define NB 2
#define SQ 2048
#define MR (NB*SQ)   // 4096 token rows

// ---------------- scratch (device globals: allocation-free) ----------------
__device__ float g_qn[(size_t)MR*DM];
__device__ float g_kn[(size_t)MR*DM];
__device__ float g_vn[(size_t)MR*DM];
__device__ float g_q [(size_t)MR*DM];
__device__ float g_k [(size_t)MR*DM];
__device__ float g_v [(size_t)MR*DM];
__device__ float g_ctx[(size_t)MR*DM];
__device__ float g_wb[(size_t)NB*SQ*SQ];   // pre-scaled relation bias

// ---------------- tf32 helpers ----------------
static __device__ __forceinline__ unsigned f2tf(float x){
    unsigned u; asm("cvt.rna.tf32.f32 %0, %1;" : "=r"(u) : "f"(x)); return u;
}
static __device__ __forceinline__ float f2tff(float x){ return __uint_as_float(f2tf(x)); }

static __device__ __forceinline__ void mma8(float* d,
        unsigned a0, unsigned a1, unsigned a2, unsigned a3,
        unsigned b0, unsigned b1){
    asm volatile("mma.sync.aligned.m16n8k8.row.col.f32.tf32.tf32.f32 "
        "{%0,%1,%2,%3}, {%4,%5,%6,%7}, {%8,%9}, {%0,%1,%2,%3};\n"
        : "+f"(d[0]), "+f"(d[1]), "+f"(d[2]), "+f"(d[3])
        : "r"(a0), "r"(a1), "r"(a2), "r"(a3), "r"(b0), "r"(b1));
}

#define CP_COMMIT() asm volatile("cp.async.commit_group;\n" ::: "memory")
#define CP_WAIT(n)  asm volatile("cp.async.wait_group %0;\n" :: "n"(n) : "memory")

// ---------------- LayerNorm (shared gamma/beta) ----------------
__global__ __launch_bounds__(256) void ln_kernel(
    const float* __restrict__ q, const float* __restrict__ k, const float* __restrict__ v,
    const float* __restrict__ gamma, const float* __restrict__ beta)
{
    int row = blockIdx.x;
    const float* src; float* dst;
    if (blockIdx.y == 0){ src = q; dst = g_qn; }
    else if (blockIdx.y == 1){ src = k; dst = g_kn; }
    else { src = v; dst = g_vn; }

    const float4 xv = ((const float4*)(src + (size_t)row*DM))[threadIdx.x];
    float s  = xv.x + xv.y + xv.z + xv.w;
    float sq = xv.x*xv.x + xv.y*xv.y + xv.z*xv.z + xv.w*xv.w;
    #pragma unroll
    for (int o = 16; o; o >>= 1){
        s  += __shfl_xor_sync(0xffffffffu, s,  o);
        sq += __shfl_xor_sync(0xffffffffu, sq, o);
    }
    __shared__ float rs[8], rq[8];
    int w = threadIdx.x >> 5, lane = threadIdx.x & 31;
    if (!lane){ rs[w] = s; rq[w] = sq; }
    __syncthreads();
    if (threadIdx.x == 0){
        float ts = 0.f, tq = 0.f;
        #pragma unroll
        for (int i = 0; i < 8; ++i){ ts += rs[i]; tq += rq[i]; }
        float mu  = ts * (1.f/DM);
        float var = tq * (1.f/DM) - mu*mu;
        rs[0] = mu; rq[0] = rsqrtf(var + 1e-5f);
    }
    __syncthreads();
    float mu = rs[0], rstd = rq[0];
    const float4 g4 = ((const float4*)gamma)[threadIdx.x];
    const float4 b4 = ((const float4*)beta )[threadIdx.x];
    float4 o;
    o.x = (xv.x - mu)*rstd*g4.x + b4.x;
    o.y = (xv.y - mu)*rstd*g4.y + b4.y;
    o.z = (xv.z - mu)*rstd*g4.z + b4.z;
    o.w = (xv.w - mu)*rstd*g4.w + b4.w;
    ((float4*)(dst + (size_t)row*DM))[threadIdx.x] = o;
}

// ---------------- relation bias ----------------
__global__ __launch_bounds__(256) void wbias_kernel(
    const float4* __restrict__ tr, const float* __restrict__ rtw, const float* __restrict__ rsc)
{
    float w0 = rtw[0], w1 = rtw[1], w2 = rtw[2], w3 = rtw[3];
    float mx = fmaxf(fmaxf(w0,w1), fmaxf(w2,w3));
    float e0 = expf(w0-mx), e1 = expf(w1-mx), e2 = expf(w2-mx), e3 = expf(w3-mx);
    float bs = 0.1f / (1.f + expf(-rsc[0]));
    float inv = bs / (e0+e1+e2+e3);
    float r0 = e0*inv, r1 = e1*inv, r2 = e2*inv, r3 = e3*inv;
    size_t i = (size_t)blockIdx.x*256 + threadIdx.x;
    float4 t = tr[i];
    g_wb[i] = t.x*r0 + t.y*r1 + t.z*r2 + t.w*r3;
}

// ---------------- TF32 GEMM body: C[4096,1024] = A @ W^T + bias ----------------
static __device__ __forceinline__ void gemm_body(
    const float* __restrict__ A, const float* __restrict__ W,
    const float* __restrict__ bias, float* __restrict__ C,
    float (*As)[128][20], float (*Bs)[128][20])
{
    const int tid = threadIdx.x, lane = tid & 31, wid = tid >> 5;
    const int wm = wid >> 1, wn = wid & 1;
    const int bm = blockIdx.y*128, bn = blockIdx.x*128;

    float acc[2][8][4];
    #pragma unroll
    for (int mt = 0; mt < 2; ++mt)
        #pragma unroll
        for (int nt = 0; nt < 8; ++nt)
            #pragma unroll
            for (int e = 0; e < 4; ++e) acc[mt][nt][e] = 0.f;

    const int lr = tid >> 2, lc = (tid & 3)*4;
    float4 ra[2], rb[2];

    #define FETCH(kt) do { \
        const float* Ap = A + (size_t)(bm+lr)*1024 + (kt)*16 + lc; \
        ra[0] = *(const float4*)Ap; ra[1] = *(const float4*)(Ap + (size_t)64*1024); \
        const float* Wp = W + (size_t)(bn+lr)*1024 + (kt)*16 + lc; \
        rb[0] = *(const float4*)Wp; rb[1] = *(const float4*)(Wp + (size_t)64*1024); \
    } while(0)
    #define STORE(st) do { \
        *(float4*)&As[st][lr   ][lc] = make_float4(f2tff(ra[0].x), f2tff(ra[0].y), f2tff(ra[0].z), f2tff(ra[0].w)); \
        *(float4*)&As[st][lr+64][lc] = make_float4(f2tff(ra[1].x), f2tff(ra[1].y), f2tff(ra[1].z), f2tff(ra[1].w)); \
        *(float4*)&Bs[st][lr   ][lc] = make_float4(f2tff(rb[0].x), f2tff(rb[0].y), f2tff(rb[0].z), f2tff(rb[0].w)); \
        *(float4*)&Bs[st][lr+64][lc] = make_float4(f2tff(rb[1].x), f2tff(rb[1].y), f2tff(rb[1].z), f2tff(rb[1].w)); \
    } while(0)

    FETCH(0); STORE(0); __syncthreads();

    for (int kt = 0; kt < 64; ++kt){
        const int cur = kt & 1;
        if (kt < 63) FETCH(kt+1);
        #pragma unroll
        for (int ks = 0; ks < 2; ++ks){
            const int k0 = ks*8 + (lane & 3);
            unsigned af[2][4], bf[8][2];
            #pragma unroll
            for (int mt = 0; mt < 2; ++mt){
                int r = wm*32 + mt*16 + (lane >> 2);
                af[mt][0] = __float_as_uint(As[cur][r  ][k0  ]);
                af[mt][1] = __float_as_uint(As[cur][r+8][k0  ]);
                af[mt][2] = __float_as_uint(As[cur][r  ][k0+4]);
                af[mt][3] = __float_as_uint(As[cur][r+8][k0+4]);
            }
            #pragma unroll
            for (int nt = 0; nt < 8; ++nt){
                int n = wn*64 + nt*8 + (lane >> 2);
                bf[nt][0] = __float_as_uint(Bs[cur][n][k0  ]);
                bf[nt][1] = __float_as_uint(Bs[cur][n][k0+4]);
            }
            #pragma unroll
            for (int mt = 0; mt < 2; ++mt)
                #pragma unroll
                for (int nt = 0; nt < 8; ++nt)
                    mma8(acc[mt][nt], af[mt][0], af[mt][1], af[mt][2], af[mt][3],
                         bf[nt][0], bf[nt][1]);
        }
        if (kt < 63) STORE(cur ^ 1);
        __syncthreads();
    }
    #undef FETCH
    #undef STORE

    #pragma unroll
    for (int mt = 0; mt < 2; ++mt)
        #pragma unroll
        for (int nt = 0; nt < 8; ++nt)
            #pragma unroll
            for (int e = 0; e < 4; ++e){
                int r = bm + wm*32 + mt*16 + (lane >> 2) + ((e >> 1) << 3);
                int c = bn + wn*64 + nt*8 + (lane & 3)*2 + (e & 1);
                C[(size_t)r*1024 + c] = acc[mt][nt][e] + bias[c];
            }
}

// merged QKV projections: blockIdx.z selects which of the 3 GEMMs
__global__ __launch_bounds__(256,2) void gemm_qkv(
    const float* __restrict__ bq, const float* __restrict__ bk, const float* __restrict__ bv,
    const float* __restrict__ Wq, const float* __restrict__ Wk, const float* __restrict__ Wv)
{
    __shared__ __align__(16) float As[2][128][20];
    __shared__ __align__(16) float Bs[2][128][20];
    const float *A, *W, *bias; float* C;
    if (blockIdx.z == 0){ A = g_qn; W = Wq; bias = bq; C = g_q; }
    else if (blockIdx.z == 1){ A = g_kn; W = Wk; bias = bk; C = g_k; }
    else { A = g_vn; W = Wv; bias = bv; C = g_v; }
    gemm_body(A, W, bias, C, As, Bs);
}

__global__ __launch_bounds__(256,2) void gemm_tf32(
    const float* __restrict__ A, const float* __restrict__ W,
    const float* __restrict__ bias, float* __restrict__ C)
{
    __shared__ __align__(16) float As[2][128][20];
    __shared__ __align__(16) float Bs[2][128][20];
    gemm_body(A, W, bias, C, As, Bs);
}

// ---------------- fused attention: register scores + 4-deep unified K|V pipeline ----------------
#define KVP   68
#define KVSZ  (128*KVP)
#define NSTG  4

static __device__ __forceinline__ void cp_tile(float* dstbuf, const float* src_base, int tid){
    #pragma unroll
    for (int j = 0; j < 4; ++j){
        int idx = tid + j*512;
        int r = idx >> 4, c = (idx & 15)*4;
        uint32_t daddr = (uint32_t)__cvta_generic_to_shared(dstbuf + r*KVP + c);
        const float* s = src_base + (size_t)r*DM + c;
        asm volatile("cp.async.cg.shared.global [%0], [%1], 16;\n" :: "r"(daddr), "l"(s) : "memory");
    }
}

__global__ __launch_bounds__(512) void attn_kernel(
    const int* __restrict__ mask, float* __restrict__ attnw)
{
    extern __shared__ float smem[];
    float* KV  = smem;                 // [NSTG][128][KVP] = 139.3KB
    float* Qs  = KV + NSTG*KVSZ;       // [16][72]
    float* red = Qs + 16*72;           // [8][1024] O-reduction = 32KB
    float* mx  = red + 8*1024;         // [16][16]
    float* sm  = mx + 256;             // [16][16]

    const int b = blockIdx.z, h = blockIdx.y, q0 = blockIdx.x*16;
    const int tid = threadIdx.x, lane = tid & 31, w = tid >> 5;
    const int u = lane & 3, r0 = lane >> 2;

    const float* Kbase = g_k + ((size_t)b*SQ)*DM + h*HD;
    const float* Vbase = g_v + ((size_t)b*SQ)*DM + h*HD;

    // unified stream: tiles 0..15 = K, 16..31 = V
    #define SRC(sidx) ((sidx) < 16 ? Kbase + (size_t)(sidx)*128*DM \
                                   : Vbase + (size_t)((sidx)-16)*128*DM)

    // load + tf32-round Q tile (16 x 64)
    if (tid < 256){
        int r = tid >> 4, c4 = tid & 15;
        const float* qb = g_q + ((size_t)(b*SQ + q0 + r))*DM + h*HD + c4*4;
        float4 v = *(const float4*)qb;
        *(float4*)&Qs[r*72 + c4*4] =
            make_float4(f2tff(v.x), f2tff(v.y), f2tff(v.z), f2tff(v.w));
    }

    // prefetch streams 0,1,2
    cp_tile(KV + 0*KVSZ, SRC(0), tid); CP_COMMIT();
    cp_tile(KV + 1*KVSZ, SRC(1), tid); CP_COMMIT();
    cp_tile(KV + 2*KVSZ, SRC(2), tid); CP_COMMIT();
    __syncthreads();

    // preload Q fragments
    unsigned qa[8][4];
    #pragma unroll
    for (int ks = 0; ks < 8; ++ks){
        int ak = ks*8 + u;
        qa[ks][0] = __float_as_uint(Qs[ r0   *72 + ak  ]);
        qa[ks][1] = __float_as_uint(Qs[(r0+8)*72 + ak  ]);
        qa[ks][2] = __float_as_uint(Qs[ r0   *72 + ak+4]);
        qa[ks][3] = __float_as_uint(Qs[(r0+8)*72 + ak+4]);
    }

    float s[16][4];   // register-resident score slice

    const float* wbr0 = g_wb + ((size_t)(b*SQ + q0 + r0    ))*SQ;
    const float* wbr1 = g_wb + ((size_t)(b*SQ + q0 + r0 + 8))*SQ;
    const int*   mkb  = mask + (size_t)b*SQ;

    // ---- Phase 1: scores = QK^T/8 + bias, masked -> registers (streams 0..15) ----
    #pragma unroll
    for (int t = 0; t < 16; ++t){
        CP_WAIT(2);
        __syncthreads();
        // refill buffer consumed last iteration with stream t+3 (always valid: t+3 <= 18 < 32)
        cp_tile(KV + ((t+3) & 3)*KVSZ, SRC(t+3), tid); CP_COMMIT();
        {
            const float* Bp = KV + (t & 3)*KVSZ + (w*8 + r0)*KVP + u;
            float acc[4] = {0.f, 0.f, 0.f, 0.f};
            #pragma unroll
            for (int ks = 0; ks < 8; ++ks){
                unsigned b0 = f2tf(Bp[ks*8    ]);
                unsigned b1 = f2tf(Bp[ks*8 + 4]);
                mma8(acc, qa[ks][0], qa[ks][1], qa[ks][2], qa[ks][3], b0, b1);
            }
            const int cg = t*128 + w*8 + 2*u;
            float2 w0 = *(const float2*)(wbr0 + cg);
            float2 w1 = *(const float2*)(wbr1 + cg);
            int2   mk = *(const int2*)(mkb + cg);
            s[t][0] = mk.x ? fmaf(acc[0], 0.125f, w0.x) : -1e9f;
            s[t][1] = mk.y ? fmaf(acc[1], 0.125f, w0.y) : -1e9f;
            s[t][2] = mk.x ? fmaf(acc[2], 0.125f, w1.x) : -1e9f;
            s[t][3] = mk.y ? fmaf(acc[3], 0.125f, w1.y) : -1e9f;
        }
    }

    // ---- Phase 2: softmax over registers + stream attn_weights ----
    // (streams 16,17,18 = V tiles 0,1,2 are in flight, landing during this phase)
    {
        float lm0 = -1e30f, lm1 = -1e30f;
        #pragma unroll
        for (int t = 0; t < 16; ++t){
            lm0 = fmaxf(lm0, fmaxf(s[t][0], s[t][1]));
            lm1 = fmaxf(lm1, fmaxf(s[t][2], s[t][3]));
        }
        lm0 = fmaxf(lm0, __shfl_xor_sync(0xffffffffu, lm0, 1));
        lm0 = fmaxf(lm0, __shfl_xor_sync(0xffffffffu, lm0, 2));
        lm1 = fmaxf(lm1, __shfl_xor_sync(0xffffffffu, lm1, 1));
        lm1 = fmaxf(lm1, __shfl_xor_sync(0xffffffffu, lm1, 2));
        if (u == 0){ mx[w*16 + r0] = lm0; mx[w*16 + r0 + 8] = lm1; }
        __syncthreads();
        float M0 = -1e30f, M1 = -1e30f;
        #pragma unroll
        for (int i = 0; i < 16; ++i){
            M0 = fmaxf(M0, mx[i*16 + r0]);
            M1 = fmaxf(M1, mx[i*16 + r0 + 8]);
        }
        float s0 = 0.f, s1 = 0.f;
        #pragma unroll
        for (int t = 0; t < 16; ++t){
            s[t][0] = __expf(s[t][0] - M0);
            s[t][1] = __expf(s[t][1] - M0);
            s[t][2] = __expf(s[t][2] - M1);
            s[t][3] = __expf(s[t][3] - M1);
            s0 += s[t][0] + s[t][1];
            s1 += s[t][2] + s[t][3];
        }
        s0 += __shfl_xor_sync(0xffffffffu, s0, 1);
        s0 += __shfl_xor_sync(0xffffffffu, s0, 2);
        s1 += __shfl_xor_sync(0xffffffffu, s1, 1);
        s1 += __shfl_xor_sync(0xffffffffu, s1, 2);
        if (u == 0){ sm[w*16 + r0] = s0; sm[w*16 + r0 + 8] = s1; }
        __syncthreads();
        float S0 = 0.f, S1 = 0.f;
        #pragma unroll
        for (int i = 0; i < 16; ++i){
            S0 += sm[i*16 + r0];
            S1 += sm[i*16 + r0 + 8];
        }
        float i0 = 1.f / S0, i1 = 1.f / S1;
        float* o0 = attnw + (((size_t)(b*NH + h)*SQ + q0 + r0    ))*SQ + w*8 + 2*u;
        float* o1 = attnw + (((size_t)(b*NH + h)*SQ + q0 + r0 + 8))*SQ + w*8 + 2*u;
        #pragma unroll
        for (int t = 0; t < 16; ++t){
            s[t][0] *= i0; s[t][1] *= i0;
            s[t][2] *= i1; s[t][3] *= i1;
            *(float2*)(o0 + t*128) = make_float2(s[t][0], s[t][1]);
            *(float2*)(o1 + t*128) = make_float2(s[t][2], s[t][3]);
        }
    }

    // ---- Phase 3: partial O = P_slice @ V_slice per warp (streams 16..31) ----
    float oacc[8][4];
    #pragma unroll
    for (int nb = 0; nb < 8; ++nb)
        #pragma unroll
        for (int e = 0; e < 4; ++e) oacc[nb][e] = 0.f;

    const int src1 = (lane & ~3) | (u >> 1);
    const int src2 = src1 + 2;

    #pragma unroll
    for (int t = 0; t < 16; ++t){
        if (t < 14) CP_WAIT(2);
        else if (t == 14) CP_WAIT(1);
        else CP_WAIT(0);
        __syncthreads();
        if (t + 3 < 16){
            cp_tile(KV + ((t+3) & 3)*KVSZ, SRC(16 + t + 3), tid); CP_COMMIT();
        }
        {
            const int st = 16 + t;
            // C-layout -> A-layout: gather cols u, u+4 of the warp's 8-col block
            float t00 = __shfl_sync(0xffffffffu, s[t][0], src1);
            float t01 = __shfl_sync(0xffffffffu, s[t][1], src1);
            float t10 = __shfl_sync(0xffffffffu, s[t][2], src1);
            float t11 = __shfl_sync(0xffffffffu, s[t][3], src1);
            float v00 = __shfl_sync(0xffffffffu, s[t][0], src2);
            float v01 = __shfl_sync(0xffffffffu, s[t][1], src2);
            float v10 = __shfl_sync(0xffffffffu, s[t][2], src2);
            float v11 = __shfl_sync(0xffffffffu, s[t][3], src2);
            unsigned a0 = f2tf((u & 1) ? t01 : t00);
            unsigned a1 = f2tf((u & 1) ? t11 : t10);
            unsigned a2 = f2tf((u & 1) ? v01 : v00);
            unsigned a3 = f2tf((u & 1) ? v11 : v10);

            const float* Vt = KV + (st & 3)*KVSZ;
            const float* Bp0 = Vt + (w*8 + u    )*KVP + r0;
            const float* Bp1 = Vt + (w*8 + u + 4)*KVP + r0;
            #pragma unroll
            for (int nb = 0; nb < 8; ++nb){
                unsigned b0 = f2tf(Bp0[nb*8]);
                unsigned b1 = f2tf(Bp1[nb*8]);
                mma8(oacc[nb], a0, a1, a2, a3, b0, b1);
            }
        }
    }
    __syncthreads();   // all warps done reading V buffers before red overlaps nothing (red is separate); barrier orders phase boundary

    // ---- tree-reduce O over 16 warps ----
    #pragma unroll
    for (int half = 8; half >= 1; half >>= 1){
        if (w >= half && w < 2*half){
            float* dst = red + (w - half)*1024 + lane*4;
            #pragma unroll
            for (int nb = 0; nb < 8; ++nb)
                *(float4*)(dst + nb*128) =
                    make_float4(oacc[nb][0], oacc[nb][1], oacc[nb][2], oacc[nb][3]);
        }
        __syncthreads();
        if (w < half){
            const float* srcp = red + w*1024 + lane*4;
            #pragma unroll
            for (int nb = 0; nb < 8; ++nb){
                float4 p = *(const float4*)(srcp + nb*128);
                oacc[nb][0] += p.x; oacc[nb][1] += p.y;
                oacc[nb][2] += p.z; oacc[nb][3] += p.w;
            }
        }
        __syncthreads();
    }

    if (w == 0){
        float* c0 = g_ctx + ((size_t)(b*SQ + q0 + r0    ))*DM + h*HD + 2*u;
        float* c1 = g_ctx + ((size_t)(b*SQ + q0 + r0 + 8))*DM + h*HD + 2*u;
        #pragma unroll
        for (int nb = 0; nb < 8; ++nb){
            *(float2*)(c0 + nb*8) = make_float2(oacc[nb][0], oacc[nb][1]);
            *(float2*)(c1 + nb*8) = make_float2(oacc[nb][2], oacc[nb][3]);
        }
    }
    #undef SRC
}

// ---------------- launcher ----------------
extern "C" void kernel_launch(void* const* d_in, const int* in_sizes, int n_in,
                              void* d_out, int out_size)
{
    const float* q     = (const float*)d_in[0];
    const float* k     = (const float*)d_in[1];
    const float* v     = (const float*)d_in[2];
    const int*   mask  = (const int*)  d_in[3];
    const float* tagr  = (const float*)d_in[4];
    const float* gamma = (const float*)d_in[5];
    const float* beta  = (const float*)d_in[6];
    const float* Wq    = (const float*)d_in[7];
    const float* bq    = (const float*)d_in[8];
    const float* Wk    = (const float*)d_in[9];
    const float* bk    = (const float*)d_in[10];
    const float* Wv    = (const float*)d_in[11];
    const float* bv    = (const float*)d_in[12];
    const float* Wo    = (const float*)d_in[13];
    const float* bo    = (const float*)d_in[14];
    const float* rtw   = (const float*)d_in[15];
    const float* rsc   = (const float*)d_in[16];

    float* out   = (float*)d_out;
    float* attnw = out + (size_t)MR*DM;

    float *p_ctx;
    cudaGetSymbolAddress((void**)&p_ctx, g_ctx);

    ln_kernel<<<dim3(MR, 3), 256>>>(q, k, v, gamma, beta);
    wbias_kernel<<<(NB*SQ*SQ)/256, 256>>>((const float4*)tagr, rtw, rsc);

    gemm_qkv<<<dim3(8, 32, 3), 256>>>(bq, bk, bv, Wq, Wk, Wv);

    const int shbytes = (NSTG*KVSZ + 16*72 + 8*1024 + 256 + 256) * 4;
    cudaFuncSetAttribute(attn_kernel, cudaFuncAttributeMaxDynamicSharedMemorySize, 200*1024);
    attn_kernel<<<dim3(SQ/16, NH, NB), 512, shbytes>>>(mask, attnw);

    gemm_tf32<<<dim3(8, 32), 256>>>(p_ctx, Wo, bo, out);
}

// round 10
// speedup vs baseline: 2.7429x; 1.1355x over previous
#include <cuda_runtime.h>
#include <math.h>
#include <stdint.h>

#define DM 1024
#define NH 16
#define HD 64
#define NB 2
#define SQ 2048
#define MR (NB*SQ)   // 4096 token rows

// ---------------- scratch (device globals: allocation-free) ----------------
__device__ float g_qn[(size_t)MR*DM];
__device__ float g_kn[(size_t)MR*DM];
__device__ float g_vn[(size_t)MR*DM];
__device__ float g_q [(size_t)MR*DM];
__device__ float g_k [(size_t)MR*DM];
__device__ float g_v [(size_t)MR*DM];
__device__ float g_ctx[(size_t)MR*DM];
__device__ float g_wb[(size_t)NB*SQ*SQ];   // pre-scaled relation bias

// ---------------- tf32 helpers ----------------
static __device__ __forceinline__ unsigned f2tf(float x){
    unsigned u; asm("cvt.rna.tf32.f32 %0, %1;" : "=r"(u) : "f"(x)); return u;
}
static __device__ __forceinline__ float f2tff(float x){ return __uint_as_float(f2tf(x)); }

static __device__ __forceinline__ void mma8(float* d,
        unsigned a0, unsigned a1, unsigned a2, unsigned a3,
        unsigned b0, unsigned b1){
    asm volatile("mma.sync.aligned.m16n8k8.row.col.f32.tf32.tf32.f32 "
        "{%0,%1,%2,%3}, {%4,%5,%6,%7}, {%8,%9}, {%0,%1,%2,%3};\n"
        : "+f"(d[0]), "+f"(d[1]), "+f"(d[2]), "+f"(d[3])
        : "r"(a0), "r"(a1), "r"(a2), "r"(a3), "r"(b0), "r"(b1));
}

#define CP_COMMIT() asm volatile("cp.async.commit_group;\n" ::: "memory")
#define CP_WAIT(n)  asm volatile("cp.async.wait_group %0;\n" :: "n"(n) : "memory")

// ---------------- LayerNorm (shared gamma/beta) ----------------
__global__ __launch_bounds__(256) void ln_kernel(
    const float* __restrict__ q, const float* __restrict__ k, const float* __restrict__ v,
    const float* __restrict__ gamma, const float* __restrict__ beta)
{
    int row = blockIdx.x;
    const float* src; float* dst;
    if (blockIdx.y == 0){ src = q; dst = g_qn; }
    else if (blockIdx.y == 1){ src = k; dst = g_kn; }
    else { src = v; dst = g_vn; }

    const float4 xv = ((const float4*)(src + (size_t)row*DM))[threadIdx.x];
    float s  = xv.x + xv.y + xv.z + xv.w;
    float sq = xv.x*xv.x + xv.y*xv.y + xv.z*xv.z + xv.w*xv.w;
    #pragma unroll
    for (int o = 16; o; o >>= 1){
        s  += __shfl_xor_sync(0xffffffffu, s,  o);
        sq += __shfl_xor_sync(0xffffffffu, sq, o);
    }
    __shared__ float rs[8], rq[8];
    int w = threadIdx.x >> 5, lane = threadIdx.x & 31;
    if (!lane){ rs[w] = s; rq[w] = sq; }
    __syncthreads();
    if (threadIdx.x == 0){
        float ts = 0.f, tq = 0.f;
        #pragma unroll
        for (int i = 0; i < 8; ++i){ ts += rs[i]; tq += rq[i]; }
        float mu  = ts * (1.f/DM);
        float var = tq * (1.f/DM) - mu*mu;
        rs[0] = mu; rq[0] = rsqrtf(var + 1e-5f);
    }
    __syncthreads();
    float mu = rs[0], rstd = rq[0];
    const float4 g4 = ((const float4*)gamma)[threadIdx.x];
    const float4 b4 = ((const float4*)beta )[threadIdx.x];
    float4 o;
    o.x = (xv.x - mu)*rstd*g4.x + b4.x;
    o.y = (xv.y - mu)*rstd*g4.y + b4.y;
    o.z = (xv.z - mu)*rstd*g4.z + b4.z;
    o.w = (xv.w - mu)*rstd*g4.w + b4.w;
    ((float4*)(dst + (size_t)row*DM))[threadIdx.x] = o;
}

// ---------------- relation bias ----------------
__global__ __launch_bounds__(256) void wbias_kernel(
    const float4* __restrict__ tr, const float* __restrict__ rtw, const float* __restrict__ rsc)
{
    float w0 = rtw[0], w1 = rtw[1], w2 = rtw[2], w3 = rtw[3];
    float mx = fmaxf(fmaxf(w0,w1), fmaxf(w2,w3));
    float e0 = expf(w0-mx), e1 = expf(w1-mx), e2 = expf(w2-mx), e3 = expf(w3-mx);
    float bs = 0.1f / (1.f + expf(-rsc[0]));
    float inv = bs / (e0+e1+e2+e3);
    float r0 = e0*inv, r1 = e1*inv, r2 = e2*inv, r3 = e3*inv;
    size_t i = (size_t)blockIdx.x*256 + threadIdx.x;
    float4 t = tr[i];
    g_wb[i] = t.x*r0 + t.y*r1 + t.z*r2 + t.w*r3;
}

// ---------------- TF32 GEMM body: C[4096,1024] = A @ W^T + bias ----------------
template<bool RND>
static __device__ __forceinline__ void gemm_body(
    const float* __restrict__ A, const float* __restrict__ W,
    const float* __restrict__ bias, float* __restrict__ C,
    float (*As)[128][20], float (*Bs)[128][20])
{
    const int tid = threadIdx.x, lane = tid & 31, wid = tid >> 5;
    const int wm = wid >> 1, wn = wid & 1;
    const int bm = blockIdx.y*128, bn = blockIdx.x*128;

    float acc[2][8][4];
    #pragma unroll
    for (int mt = 0; mt < 2; ++mt)
        #pragma unroll
        for (int nt = 0; nt < 8; ++nt)
            #pragma unroll
            for (int e = 0; e < 4; ++e) acc[mt][nt][e] = 0.f;

    const int lr = tid >> 2, lc = (tid & 3)*4;
    float4 ra[2], rb[2];

    #define FETCH(kt) do { \
        const float* Ap = A + (size_t)(bm+lr)*1024 + (kt)*16 + lc; \
        ra[0] = *(const float4*)Ap; ra[1] = *(const float4*)(Ap + (size_t)64*1024); \
        const float* Wp = W + (size_t)(bn+lr)*1024 + (kt)*16 + lc; \
        rb[0] = *(const float4*)Wp; rb[1] = *(const float4*)(Wp + (size_t)64*1024); \
    } while(0)
    #define STORE(st) do { \
        *(float4*)&As[st][lr   ][lc] = make_float4(f2tff(ra[0].x), f2tff(ra[0].y), f2tff(ra[0].z), f2tff(ra[0].w)); \
        *(float4*)&As[st][lr+64][lc] = make_float4(f2tff(ra[1].x), f2tff(ra[1].y), f2tff(ra[1].z), f2tff(ra[1].w)); \
        *(float4*)&Bs[st][lr   ][lc] = make_float4(f2tff(rb[0].x), f2tff(rb[0].y), f2tff(rb[0].z), f2tff(rb[0].w)); \
        *(float4*)&Bs[st][lr+64][lc] = make_float4(f2tff(rb[1].x), f2tff(rb[1].y), f2tff(rb[1].z), f2tff(rb[1].w)); \
    } while(0)

    FETCH(0); STORE(0); __syncthreads();

    for (int kt = 0; kt < 64; ++kt){
        const int cur = kt & 1;
        if (kt < 63) FETCH(kt+1);
        #pragma unroll
        for (int ks = 0; ks < 2; ++ks){
            const int k0 = ks*8 + (lane & 3);
            unsigned af[2][4], bf[8][2];
            #pragma unroll
            for (int mt = 0; mt < 2; ++mt){
                int r = wm*32 + mt*16 + (lane >> 2);
                af[mt][0] = __float_as_uint(As[cur][r  ][k0  ]);
                af[mt][1] = __float_as_uint(As[cur][r+8][k0  ]);
                af[mt][2] = __float_as_uint(As[cur][r  ][k0+4]);
                af[mt][3] = __float_as_uint(As[cur][r+8][k0+4]);
            }
            #pragma unroll
            for (int nt = 0; nt < 8; ++nt){
                int n = wn*64 + nt*8 + (lane >> 2);
                bf[nt][0] = __float_as_uint(Bs[cur][n][k0  ]);
                bf[nt][1] = __float_as_uint(Bs[cur][n][k0+4]);
            }
            #pragma unroll
            for (int mt = 0; mt < 2; ++mt)
                #pragma unroll
                for (int nt = 0; nt < 8; ++nt)
                    mma8(acc[mt][nt], af[mt][0], af[mt][1], af[mt][2], af[mt][3],
                         bf[nt][0], bf[nt][1]);
        }
        if (kt < 63) STORE(cur ^ 1);
        __syncthreads();
    }
    #undef FETCH
    #undef STORE

    #pragma unroll
    for (int mt = 0; mt < 2; ++mt)
        #pragma unroll
        for (int nt = 0; nt < 8; ++nt)
            #pragma unroll
            for (int e = 0; e < 4; ++e){
                int r = bm + wm*32 + mt*16 + (lane >> 2) + ((e >> 1) << 3);
                int c = bn + wn*64 + nt*8 + (lane & 3)*2 + (e & 1);
                float val = acc[mt][nt][e] + bias[c];
                C[(size_t)r*1024 + c] = RND ? f2tff(val) : val;
            }
}

// merged QKV projections (outputs pre-rounded to tf32 for the attention mma)
__global__ __launch_bounds__(256,2) void gemm_qkv(
    const float* __restrict__ bq, const float* __restrict__ bk, const float* __restrict__ bv,
    const float* __restrict__ Wq, const float* __restrict__ Wk, const float* __restrict__ Wv)
{
    __shared__ __align__(16) float As[2][128][20];
    __shared__ __align__(16) float Bs[2][128][20];
    const float *A, *W, *bias; float* C;
    if (blockIdx.z == 0){ A = g_qn; W = Wq; bias = bq; C = g_q; }
    else if (blockIdx.z == 1){ A = g_kn; W = Wk; bias = bk; C = g_k; }
    else { A = g_vn; W = Wv; bias = bv; C = g_v; }
    gemm_body<true>(A, W, bias, C, As, Bs);
}

__global__ __launch_bounds__(256,2) void gemm_tf32(
    const float* __restrict__ A, const float* __restrict__ W,
    const float* __restrict__ bias, float* __restrict__ C)
{
    __shared__ __align__(16) float As[2][128][20];
    __shared__ __align__(16) float Bs[2][128][20];
    gemm_body<false>(A, W, bias, C, As, Bs);
}

// ---------------- fused attention: register scores + per-warp private pipelines ----------------
// 512 threads, 16 warps. Warp w owns key-rows [w*8, w*8+8) of every 128-key tile —
// its K/V slices are warp-private, so the 32-tile mainloop needs NO block barriers.
#define KVP   68
#define KVSZ  (128*KVP)
#define NSTG  4

// per-warp cp.async of the warp's own 8-row x 64-col slice (4 cp per lane)
static __device__ __forceinline__ void cp_warp(float* dstbuf, const float* src_base, int w, int lane){
    #pragma unroll
    for (int j = 0; j < 4; ++j){
        int idx = lane + j*32;            // 0..127
        int r = w*8 + (idx >> 4);         // warp's rows
        int c = (idx & 15)*4;
        uint32_t daddr = (uint32_t)__cvta_generic_to_shared(dstbuf + r*KVP + c);
        const float* s = src_base + (size_t)r*DM + c;
        asm volatile("cp.async.cg.shared.global [%0], [%1], 16;\n" :: "r"(daddr), "l"(s) : "memory");
    }
}

__global__ __launch_bounds__(512) void attn_kernel(
    const int* __restrict__ mask, float* __restrict__ attnw)
{
    extern __shared__ float smem[];
    float* KV  = smem;                 // [NSTG][128][KVP] = 139.3KB
    float* Qs  = KV + NSTG*KVSZ;       // [16][72]
    float* mx  = Qs + 16*72;           // [16][16]
    float* sm  = mx + 256;             // [16][16]
    float* red = smem;                 // O-reduction buffer, aliased onto KV (after barrier)

    const int b = blockIdx.z, h = blockIdx.y, q0 = blockIdx.x*16;
    const int tid = threadIdx.x, lane = tid & 31, w = tid >> 5;
    const int u = lane & 3, r0 = lane >> 2;

    const float* Kbase = g_k + ((size_t)b*SQ)*DM + h*HD;
    const float* Vbase = g_v + ((size_t)b*SQ)*DM + h*HD;

    // unified per-warp stream: tiles 0..15 = K, 16..31 = V
    #define SRC(sidx) ((sidx) < 16 ? Kbase + (size_t)(sidx)*128*DM \
                                   : Vbase + (size_t)((sidx)-16)*128*DM)

    // load Q tile (16 x 64) — already tf32-rounded by gemm_qkv
    if (tid < 256){
        int r = tid >> 4, c4 = tid & 15;
        const float* qb = g_q + ((size_t)(b*SQ + q0 + r))*DM + h*HD + c4*4;
        *(float4*)&Qs[r*72 + c4*4] = *(const float4*)qb;
    }

    // per-warp prefetch of streams 0,1,2 (3 private groups)
    cp_warp(KV + 0*KVSZ, SRC(0), w, lane); CP_COMMIT();
    cp_warp(KV + 1*KVSZ, SRC(1), w, lane); CP_COMMIT();
    cp_warp(KV + 2*KVSZ, SRC(2), w, lane); CP_COMMIT();
    __syncthreads();   // Qs visible to all warps

    // preload Q fragments
    unsigned qa[8][4];
    #pragma unroll
    for (int ks = 0; ks < 8; ++ks){
        int ak = ks*8 + u;
        qa[ks][0] = __float_as_uint(Qs[ r0   *72 + ak  ]);
        qa[ks][1] = __float_as_uint(Qs[(r0+8)*72 + ak  ]);
        qa[ks][2] = __float_as_uint(Qs[ r0   *72 + ak+4]);
        qa[ks][3] = __float_as_uint(Qs[(r0+8)*72 + ak+4]);
    }

    float s[16][4];   // register-resident score slice

    const float* wbr0 = g_wb + ((size_t)(b*SQ + q0 + r0    ))*SQ;
    const float* wbr1 = g_wb + ((size_t)(b*SQ + q0 + r0 + 8))*SQ;
    const int*   mkb  = mask + (size_t)b*SQ;

    // ---- Phase 1: scores = QK^T/8 + bias, masked -> registers (streams 0..15) ----
    // NO block barriers: each warp consumes/refills only its own 8-row slice.
    #pragma unroll
    for (int t = 0; t < 16; ++t){
        CP_WAIT(2);
        cp_warp(KV + ((t+3) & 3)*KVSZ, SRC(t+3), w, lane); CP_COMMIT();
        {
            const float* Bp = KV + (t & 3)*KVSZ + (w*8 + r0)*KVP + u;
            float acc[4] = {0.f, 0.f, 0.f, 0.f};
            #pragma unroll
            for (int ks = 0; ks < 8; ++ks){
                unsigned b0 = __float_as_uint(Bp[ks*8    ]);   // K pre-rounded
                unsigned b1 = __float_as_uint(Bp[ks*8 + 4]);
                mma8(acc, qa[ks][0], qa[ks][1], qa[ks][2], qa[ks][3], b0, b1);
            }
            const int cg = t*128 + w*8 + 2*u;
            float2 w0 = *(const float2*)(wbr0 + cg);
            float2 w1 = *(const float2*)(wbr1 + cg);
            int2   mk = *(const int2*)(mkb + cg);
            s[t][0] = mk.x ? fmaf(acc[0], 0.125f, w0.x) : -1e9f;
            s[t][1] = mk.y ? fmaf(acc[1], 0.125f, w0.y) : -1e9f;
            s[t][2] = mk.x ? fmaf(acc[2], 0.125f, w1.x) : -1e9f;
            s[t][3] = mk.y ? fmaf(acc[3], 0.125f, w1.y) : -1e9f;
        }
    }
    // streams 16,17,18 (V tiles 0..2) are in flight; they land during softmax

    // ---- Phase 2: softmax over registers + stream attn_weights ----
    {
        float lm0 = -1e30f, lm1 = -1e30f;
        #pragma unroll
        for (int t = 0; t < 16; ++t){
            lm0 = fmaxf(lm0, fmaxf(s[t][0], s[t][1]));
            lm1 = fmaxf(lm1, fmaxf(s[t][2], s[t][3]));
        }
        lm0 = fmaxf(lm0, __shfl_xor_sync(0xffffffffu, lm0, 1));
        lm0 = fmaxf(lm0, __shfl_xor_sync(0xffffffffu, lm0, 2));
        lm1 = fmaxf(lm1, __shfl_xor_sync(0xffffffffu, lm1, 1));
        lm1 = fmaxf(lm1, __shfl_xor_sync(0xffffffffu, lm1, 2));
        if (u == 0){ mx[w*16 + r0] = lm0; mx[w*16 + r0 + 8] = lm1; }
        __syncthreads();
        float M0 = -1e30f, M1 = -1e30f;
        #pragma unroll
        for (int i = 0; i < 16; ++i){
            M0 = fmaxf(M0, mx[i*16 + r0]);
            M1 = fmaxf(M1, mx[i*16 + r0 + 8]);
        }
        float s0 = 0.f, s1 = 0.f;
        #pragma unroll
        for (int t = 0; t < 16; ++t){
            s[t][0] = __expf(s[t][0] - M0);
            s[t][1] = __expf(s[t][1] - M0);
            s[t][2] = __expf(s[t][2] - M1);
            s[t][3] = __expf(s[t][3] - M1);
            s0 += s[t][0] + s[t][1];
            s1 += s[t][2] + s[t][3];
        }
        s0 += __shfl_xor_sync(0xffffffffu, s0, 1);
        s0 += __shfl_xor_sync(0xffffffffu, s0, 2);
        s1 += __shfl_xor_sync(0xffffffffu, s1, 1);
        s1 += __shfl_xor_sync(0xffffffffu, s1, 2);
        if (u == 0){ sm[w*16 + r0] = s0; sm[w*16 + r0 + 8] = s1; }
        __syncthreads();
        float S0 = 0.f, S1 = 0.f;
        #pragma unroll
        for (int i = 0; i < 16; ++i){
            S0 += sm[i*16 + r0];
            S1 += sm[i*16 + r0 + 8];
        }
        float i0 = 1.f / S0, i1 = 1.f / S1;
        float* o0 = attnw + (((size_t)(b*NH + h)*SQ + q0 + r0    ))*SQ + w*8 + 2*u;
        float* o1 = attnw + (((size_t)(b*NH + h)*SQ + q0 + r0 + 8))*SQ + w*8 + 2*u;
        #pragma unroll
        for (int t = 0; t < 16; ++t){
            s[t][0] *= i0; s[t][1] *= i0;
            s[t][2] *= i1; s[t][3] *= i1;
            *(float2*)(o0 + t*128) = make_float2(s[t][0], s[t][1]);
            *(float2*)(o1 + t*128) = make_float2(s[t][2], s[t][3]);
        }
    }

    // ---- Phase 3: partial O = P_slice @ V_slice per warp (streams 16..31) ----
    float oacc[8][4];
    #pragma unroll
    for (int nb = 0; nb < 8; ++nb)
        #pragma unroll
        for (int e = 0; e < 4; ++e) oacc[nb][e] = 0.f;

    const int src1 = (lane & ~3) | (u >> 1);
    const int src2 = src1 + 2;

    #pragma unroll
    for (int t = 16; t < 32; ++t){
        if (t <= 29) CP_WAIT(2);
        else if (t == 30) CP_WAIT(1);
        else CP_WAIT(0);
        if (t + 3 < 32){
            cp_warp(KV + ((t+3) & 3)*KVSZ, SRC(t+3), w, lane); CP_COMMIT();
        }
        {
            const int pt = t - 16;
            float t00 = __shfl_sync(0xffffffffu, s[pt][0], src1);
            float t01 = __shfl_sync(0xffffffffu, s[pt][1], src1);
            float t10 = __shfl_sync(0xffffffffu, s[pt][2], src1);
            float t11 = __shfl_sync(0xffffffffu, s[pt][3], src1);
            float v00 = __shfl_sync(0xffffffffu, s[pt][0], src2);
            float v01 = __shfl_sync(0xffffffffu, s[pt][1], src2);
            float v10 = __shfl_sync(0xffffffffu, s[pt][2], src2);
            float v11 = __shfl_sync(0xffffffffu, s[pt][3], src2);
            unsigned a0 = f2tf((u & 1) ? t01 : t00);
            unsigned a1 = f2tf((u & 1) ? t11 : t10);
            unsigned a2 = f2tf((u & 1) ? v01 : v00);
            unsigned a3 = f2tf((u & 1) ? v11 : v10);

            const float* Vt = KV + (t & 3)*KVSZ;
            const float* Bp0 = Vt + (w*8 + u    )*KVP + r0;
            const float* Bp1 = Vt + (w*8 + u + 4)*KVP + r0;
            #pragma unroll
            for (int nb = 0; nb < 8; ++nb){
                unsigned b0 = __float_as_uint(Bp0[nb*8]);   // V pre-rounded
                unsigned b1 = __float_as_uint(Bp1[nb*8]);
                mma8(oacc[nb], a0, a1, a2, a3, b0, b1);
            }
        }
    }
    __syncthreads();   // everyone done with KV; red (aliased) is now safe

    // ---- tree-reduce O over 16 warps ----
    #pragma unroll
    for (int half = 8; half >= 1; half >>= 1){
        if (w >= half && w < 2*half){
            float* dst = red + (w - half)*1024 + lane*4;
            #pragma unroll
            for (int nb = 0; nb < 8; ++nb)
                *(float4*)(dst + nb*128) =
                    make_float4(oacc[nb][0], oacc[nb][1], oacc[nb][2], oacc[nb][3]);
        }
        __syncthreads();
        if (w < half){
            const float* srcp = red + w*1024 + lane*4;
            #pragma unroll
            for (int nb = 0; nb < 8; ++nb){
                float4 p = *(const float4*)(srcp + nb*128);
                oacc[nb][0] += p.x; oacc[nb][1] += p.y;
                oacc[nb][2] += p.z; oacc[nb][3] += p.w;
            }
        }
        __syncthreads();
    }

    if (w == 0){
        float* c0 = g_ctx + ((size_t)(b*SQ + q0 + r0    ))*DM + h*HD + 2*u;
        float* c1 = g_ctx + ((size_t)(b*SQ + q0 + r0 + 8))*DM + h*HD + 2*u;
        #pragma unroll
        for (int nb = 0; nb < 8; ++nb){
            *(float2*)(c0 + nb*8) = make_float2(oacc[nb][0], oacc[nb][1]);
            *(float2*)(c1 + nb*8) = make_float2(oacc[nb][2], oacc[nb][3]);
        }
    }
    #undef SRC
}

// ---------------- launcher ----------------
extern "C" void kernel_launch(void* const* d_in, const int* in_sizes, int n_in,
                              void* d_out, int out_size)
{
    const float* q     = (const float*)d_in[0];
    const float* k     = (const float*)d_in[1];
    const float* v     = (const float*)d_in[2];
    const int*   mask  = (const int*)  d_in[3];
    const float* tagr  = (const float*)d_in[4];
    const float* gamma = (const float*)d_in[5];
    const float* beta  = (const float*)d_in[6];
    const float* Wq    = (const float*)d_in[7];
    const float* bq    = (const float*)d_in[8];
    const float* Wk    = (const float*)d_in[9];
    const float* bk    = (const float*)d_in[10];
    const float* Wv    = (const float*)d_in[11];
    const float* bv    = (const float*)d_in[12];
    const float* Wo    = (const float*)d_in[13];
    const float* bo    = (const float*)d_in[14];
    const float* rtw   = (const float*)d_in[15];
    const float* rsc   = (const float*)d_in[16];

    float* out   = (float*)d_out;
    float* attnw = out + (size_t)MR*DM;

    float *p_ctx;
    cudaGetSymbolAddress((void**)&p_ctx, g_ctx);

    ln_kernel<<<dim3(MR, 3), 256>>>(q, k, v, gamma, beta);
    wbias_kernel<<<(NB*SQ*SQ)/256, 256>>>((const float4*)tagr, rtw, rsc);

    gemm_qkv<<<dim3(8, 32, 3), 256>>>(bq, bk, bv, Wq, Wk, Wv);

    const int shbytes = (NSTG*KVSZ + 16*72 + 256 + 256) * 4;
    cudaFuncSetAttribute(attn_kernel, cudaFuncAttributeMaxDynamicSharedMemorySize, 152*1024);
    attn_kernel<<<dim3(SQ/16, NH, NB), 512, shbytes>>>(mask, attnw);

    gemm_tf32<<<dim3(8, 32), 256>>>(p_ctx, Wo, bo, out);
}